// round 6
// baseline (speedup 1.0000x reference)
#include <cuda_runtime.h>

// ---------------------------------------------------------------------------
// MultiheadAttention: B=2, S=2048, D=1024, H=16, Dh=64
//   Q = q@Wq+bq ; K = k@Wk+bk ; V = v@Wv+bv       (proj3_kernel, grid.z=3)
//   per (b,h): O = softmax(mask(QK^T/8)) @ V      (attn_kernel, flash-style)
//   out = O@Wo + bo                               (out_gemm_kernel)
// All fp32 SIMT this round (rel_err budget 1e-3 rules out naive bf16 MMA).
// ---------------------------------------------------------------------------

#define BATCH 2
#define SEQ   2048
#define DIM   1024
#define NHEAD 16
#define HDIM  64
#define MTOT  (BATCH*SEQ)   // 4096

// Scratch (no cudaMalloc allowed): projected Q/K/V and pre-output-proj attn.
__device__ float g_Q[MTOT*DIM];
__device__ float g_K[MTOT*DIM];
__device__ float g_V[MTOT*DIM];
__device__ float g_A[MTOT*DIM];

// ======================= GEMM: C[4096,1024] = A @ W + bias =================
// 128x128 block tile, BK=16, 256 threads, 8x8 per-thread microkernel.
#define BM 128
#define BN 128
#define BK 16
#define LDT (BM+4)   // 132 floats: keeps float4 alignment, skews banks

__device__ __forceinline__ void gemm_bias_tile(
    const float* __restrict__ A, const float* __restrict__ W,
    const float* __restrict__ bias, float* __restrict__ C)
{
    __shared__ float As[BK][LDT];   // A stored transposed: As[k][m]
    __shared__ float Ws[BK][LDT];   // W natural: Ws[k][n]
    const int t = threadIdx.x;                   // 0..255
    const int mBase = blockIdx.y * BM;
    const int nBase = blockIdx.x * BN;
    const int m0 = (t >> 4) * 8;
    const int n0 = (t & 15) * 8;

    float acc[8][8];
    #pragma unroll
    for (int i = 0; i < 8; i++)
        #pragma unroll
        for (int j = 0; j < 8; j++) acc[i][j] = 0.0f;

    for (int kb = 0; kb < DIM; kb += BK) {
        // A tile 128x16 -> transposed into As[k][m]; 512 float4 loads
        #pragma unroll
        for (int i = 0; i < 2; i++) {
            int e = t + i * 256;
            int m = e >> 2, kq = e & 3;
            float4 v = *(const float4*)(A + (mBase + m) * DIM + kb + kq * 4);
            As[kq*4+0][m] = v.x; As[kq*4+1][m] = v.y;
            As[kq*4+2][m] = v.z; As[kq*4+3][m] = v.w;
        }
        // W tile 16x128 natural; coalesced float4 both sides
        #pragma unroll
        for (int i = 0; i < 2; i++) {
            int e = t + i * 256;
            int kr = e >> 5, nq = e & 31;
            *(float4*)&Ws[kr][nq*4] =
                *(const float4*)(W + (kb + kr) * DIM + nBase + nq * 4);
        }
        __syncthreads();

        #pragma unroll
        for (int kk = 0; kk < BK; kk++) {
            float a[8], bb[8];
            *(float4*)&a[0]  = *(const float4*)&As[kk][m0];
            *(float4*)&a[4]  = *(const float4*)&As[kk][m0 + 4];
            *(float4*)&bb[0] = *(const float4*)&Ws[kk][n0];
            *(float4*)&bb[4] = *(const float4*)&Ws[kk][n0 + 4];
            #pragma unroll
            for (int i = 0; i < 8; i++)
                #pragma unroll
                for (int j = 0; j < 8; j++)
                    acc[i][j] = fmaf(a[i], bb[j], acc[i][j]);
        }
        __syncthreads();
    }

    float bsv[8];
    *(float4*)&bsv[0] = *(const float4*)(bias + nBase + n0);
    *(float4*)&bsv[4] = *(const float4*)(bias + nBase + n0 + 4);
    #pragma unroll
    for (int i = 0; i < 8; i++) {
        float* crow = C + (mBase + m0 + i) * DIM + nBase + n0;
        *(float4*)(crow)     = make_float4(acc[i][0]+bsv[0], acc[i][1]+bsv[1],
                                           acc[i][2]+bsv[2], acc[i][3]+bsv[3]);
        *(float4*)(crow + 4) = make_float4(acc[i][4]+bsv[4], acc[i][5]+bsv[5],
                                           acc[i][6]+bsv[6], acc[i][7]+bsv[7]);
    }
}

__global__ void __launch_bounds__(256)
proj3_kernel(const float* __restrict__ q, const float* __restrict__ k,
             const float* __restrict__ v,
             const float* __restrict__ wq, const float* __restrict__ bq,
             const float* __restrict__ wk, const float* __restrict__ bk,
             const float* __restrict__ wv, const float* __restrict__ bv)
{
    const int z = blockIdx.z;   // uniform per block
    const float* A    = (z == 0) ? q  : (z == 1) ? k  : v;
    const float* W    = (z == 0) ? wq : (z == 1) ? wk : wv;
    const float* bias = (z == 0) ? bq : (z == 1) ? bk : bv;
    float*       C    = (z == 0) ? g_Q : (z == 1) ? g_K : g_V;
    gemm_bias_tile(A, W, bias, C);
}

__global__ void __launch_bounds__(256)
out_gemm_kernel(const float* __restrict__ wo, const float* __restrict__ bo,
                float* __restrict__ out)
{
    gemm_bias_tile(g_A, wo, bo, out);
}

// =================== Flash-style attention, 64x64 tiles =====================
// Block: 256 threads; thread (rg,cg) = (t/16, t%16) owns 4 rows x 4 cols.
// smem: Qs[64][68], Kt[64][72] (K transposed, pad 72 for conflict-light
// transpose writes), Vs[64][68], Ps[64][68].
#define Q_LD 68
#define K_LD 72
#define V_LD 68
#define P_LD 68
#define ATTN_SMEM_BYTES ((64*Q_LD + 64*K_LD + 64*V_LD + 64*P_LD) * 4) // 70656

__global__ void __launch_bounds__(256)
attn_kernel(const int* __restrict__ mask)
{
    extern __shared__ float sm[];
    float* Qs = sm;                    // stride Q_LD
    float* Kt = Qs + 64 * Q_LD;        // stride K_LD, layout [d][kk]
    float* Vs = Kt + 64 * K_LD;        // stride V_LD, layout [kk][d]
    float* Ps = Vs + 64 * V_LD;        // stride P_LD, layout [q][kk]

    const int t  = threadIdx.x;
    const int b  = blockIdx.z;
    const int h  = blockIdx.y;
    const int q0 = blockIdx.x * 64;
    const int r0 = (t >> 4) * 4;       // 4 q-rows
    const int c0 = (t & 15) * 4;       // 4 cols (kk for S/P, d for O/V)

    const float* Qg = g_Q + ((size_t)b * SEQ + q0) * DIM + h * HDIM;
    const float* Kg = g_K + (size_t)b * SEQ * DIM + h * HDIM;
    const float* Vg = g_V + (size_t)b * SEQ * DIM + h * HDIM;

    // Load Q tile once, fold in 1/sqrt(Dh)=0.125
    #pragma unroll
    for (int i = 0; i < 4; i++) {
        int e = t + i * 256;
        int r = e >> 4, dq = e & 15;
        float4 v = *(const float4*)(Qg + r * DIM + dq * 4);
        *(float4*)&Qs[r * Q_LD + dq * 4] =
            make_float4(v.x * 0.125f, v.y * 0.125f, v.z * 0.125f, v.w * 0.125f);
    }

    float acc[4][4];
    #pragma unroll
    for (int i = 0; i < 4; i++)
        #pragma unroll
        for (int j = 0; j < 4; j++) acc[i][j] = 0.0f;
    float mrow[4] = {-1e30f, -1e30f, -1e30f, -1e30f};
    float lrow[4] = {0.0f, 0.0f, 0.0f, 0.0f};

    __syncthreads();

    for (int kt = 0; kt < SEQ / 64; kt++) {
        const int k0 = kt * 64;
        // K tile -> transposed Kt[d][kk]; coalesced scalar LDG, 4-way STS
        #pragma unroll
        for (int i = 0; i < 16; i++) {
            int e = t + i * 256;
            int kk = e >> 6, d = e & 63;
            Kt[d * K_LD + kk] = Kg[(size_t)(k0 + kk) * DIM + d];
        }
        // V tile natural layout, float4 all the way
        #pragma unroll
        for (int i = 0; i < 4; i++) {
            int e = t + i * 256;
            int kk = e >> 4, dq = e & 15;
            *(float4*)&Vs[kk * V_LD + dq * 4] =
                *(const float4*)(Vg + (size_t)(k0 + kk) * DIM + dq * 4);
        }
        __syncthreads();

        // S = (Q/8) @ K^T  — 4x4 per thread, d unrolled by 4
        float s[4][4];
        #pragma unroll
        for (int i = 0; i < 4; i++)
            #pragma unroll
            for (int j = 0; j < 4; j++) s[i][j] = 0.0f;
        #pragma unroll
        for (int d = 0; d < HDIM; d += 4) {
            float qv[4][4], kvf[4][4];
            #pragma unroll
            for (int i = 0; i < 4; i++) {
                float4 qq = *(const float4*)&Qs[(r0 + i) * Q_LD + d];
                qv[i][0] = qq.x; qv[i][1] = qq.y; qv[i][2] = qq.z; qv[i][3] = qq.w;
            }
            #pragma unroll
            for (int dd = 0; dd < 4; dd++) {
                float4 kk4 = *(const float4*)&Kt[(d + dd) * K_LD + c0];
                kvf[dd][0] = kk4.x; kvf[dd][1] = kk4.y; kvf[dd][2] = kk4.z; kvf[dd][3] = kk4.w;
            }
            #pragma unroll
            for (int i = 0; i < 4; i++)
                #pragma unroll
                for (int j = 0; j < 4; j++)
                    #pragma unroll
                    for (int dd = 0; dd < 4; dd++)
                        s[i][j] = fmaf(qv[i][dd], kvf[dd][j], s[i][j]);
        }

        // Mask + online softmax. Row group = 16 lanes (half warp); shfl_xor
        // with offsets 8,4,2,1 stays inside the 16-lane group.
        #pragma unroll
        for (int i = 0; i < 4; i++) {
            const int4 mv = *(const int4*)(mask + (size_t)(q0 + r0 + i) * SEQ + k0 + c0);
            if (mv.x == 0) s[i][0] = -1e9f;
            if (mv.y == 0) s[i][1] = -1e9f;
            if (mv.z == 0) s[i][2] = -1e9f;
            if (mv.w == 0) s[i][3] = -1e9f;
            float tmax = fmaxf(fmaxf(s[i][0], s[i][1]), fmaxf(s[i][2], s[i][3]));
            #pragma unroll
            for (int o = 8; o > 0; o >>= 1)
                tmax = fmaxf(tmax, __shfl_xor_sync(0xffffffffu, tmax, o));
            const float newm  = fmaxf(mrow[i], tmax);
            const float scale = __expf(mrow[i] - newm);
            const float p0 = __expf(s[i][0] - newm);
            const float p1 = __expf(s[i][1] - newm);
            const float p2 = __expf(s[i][2] - newm);
            const float p3 = __expf(s[i][3] - newm);
            float tsum = p0 + p1 + p2 + p3;
            #pragma unroll
            for (int o = 8; o > 0; o >>= 1)
                tsum += __shfl_xor_sync(0xffffffffu, tsum, o);
            lrow[i] = lrow[i] * scale + tsum;
            mrow[i] = newm;
            acc[i][0] *= scale; acc[i][1] *= scale;
            acc[i][2] *= scale; acc[i][3] *= scale;
            *(float4*)&Ps[(r0 + i) * P_LD + c0] = make_float4(p0, p1, p2, p3);
        }
        __syncthreads();

        // O += P @ V  — kk unrolled by 4
        #pragma unroll
        for (int kk = 0; kk < 64; kk += 4) {
            float pv[4][4], vv[4][4];
            #pragma unroll
            for (int i = 0; i < 4; i++) {
                float4 pp = *(const float4*)&Ps[(r0 + i) * P_LD + kk];
                pv[i][0] = pp.x; pv[i][1] = pp.y; pv[i][2] = pp.z; pv[i][3] = pp.w;
            }
            #pragma unroll
            for (int kkk = 0; kkk < 4; kkk++) {
                float4 v4 = *(const float4*)&Vs[(kk + kkk) * V_LD + c0];
                vv[kkk][0] = v4.x; vv[kkk][1] = v4.y; vv[kkk][2] = v4.z; vv[kkk][3] = v4.w;
            }
            #pragma unroll
            for (int i = 0; i < 4; i++)
                #pragma unroll
                for (int j = 0; j < 4; j++)
                    #pragma unroll
                    for (int kkk = 0; kkk < 4; kkk++)
                        acc[i][j] = fmaf(pv[i][kkk], vv[kkk][j], acc[i][j]);
        }
        __syncthreads();   // protect Kt/Vs/Ps before next iteration's loads
    }

    // Epilogue: normalize and write to g_A in [B,S,H*Dh] layout
    float* Og = g_A + ((size_t)b * SEQ + q0) * DIM + h * HDIM;
    #pragma unroll
    for (int i = 0; i < 4; i++) {
        const float inv = 1.0f / lrow[i];
        *(float4*)(Og + (size_t)(r0 + i) * DIM + c0) =
            make_float4(acc[i][0] * inv, acc[i][1] * inv,
                        acc[i][2] * inv, acc[i][3] * inv);
    }
}

// =============================== launch ====================================
extern "C" void kernel_launch(void* const* d_in, const int* in_sizes, int n_in,
                              void* d_out, int out_size)
{
    const float* q    = (const float*)d_in[0];
    const float* k    = (const float*)d_in[1];
    const float* v    = (const float*)d_in[2];
    const int*   mask = (const int*)  d_in[3];
    const float* w_q  = (const float*)d_in[4];
    const float* b_q  = (const float*)d_in[5];
    const float* w_k  = (const float*)d_in[6];
    const float* b_k  = (const float*)d_in[7];
    const float* w_v  = (const float*)d_in[8];
    const float* b_v  = (const float*)d_in[9];
    const float* w_o  = (const float*)d_in[10];
    const float* b_o  = (const float*)d_in[11];
    float* out = (float*)d_out;

    (void)in_sizes; (void)n_in; (void)out_size;

    // Idempotent; executed eagerly (not a stream op), safe under capture.
    cudaFuncSetAttribute(attn_kernel,
                         cudaFuncAttributeMaxDynamicSharedMemorySize,
                         ATTN_SMEM_BYTES);

    dim3 gproj(DIM / BN, MTOT / BM, 3);         // (8, 32, 3)
    proj3_kernel<<<gproj, 256>>>(q, k, v, w_q, b_q, w_k, b_k, w_v, b_v);

    dim3 gattn(SEQ / 64, NHEAD, BATCH);         // (32, 16, 2)
    attn_kernel<<<gattn, 256, ATTN_SMEM_BYTES>>>(mask);

    dim3 gout(DIM / BN, MTOT / BM, 1);          // (8, 32)
    out_gemm_kernel<<<gout, 256>>>(w_o, b_o, out);
}

// round 11
// speedup vs baseline: 1.2932x; 1.2932x over previous
#include <cuda_runtime.h>
#include <cuda_bf16.h>
#include <cstdint>

// ---------------------------------------------------------------------------
// MultiheadAttention: B=2, S=2048, D=1024, H=16, Dh=64
//   R11: tcgen05 unavailable at this PTX target (sm_103 plain). Projections
//   moved to mma.sync.m16n8k16 bf16 (HMMA) with error-compensated hi/lo split
//   (hi*hi + hi*lo + lo*hi -> fp32-accurate). cp.async double-buffered feed.
//   Attention unchanged from the passing 1812us version.
// ---------------------------------------------------------------------------

#define BATCH 2
#define SEQ   2048
#define DIM   1024
#define NHEAD 16
#define HDIM  64
#define MTOT  (BATCH*SEQ)   // 4096

// ----------------------------- device scratch ------------------------------
__device__ float g_Q[MTOT*DIM];
__device__ float g_K[MTOT*DIM];
__device__ float g_V[MTOT*DIM];
__device__ float g_A[MTOT*DIM];
__device__ __nv_bfloat16 g_in_hi[3ull*MTOT*DIM];   // split q,k,v
__device__ __nv_bfloat16 g_in_lo[3ull*MTOT*DIM];
__device__ __nv_bfloat16 g_a_hi[MTOT*DIM];          // split attention output
__device__ __nv_bfloat16 g_a_lo[MTOT*DIM];
__device__ __nv_bfloat16 g_wt_hi[4ull*DIM*DIM];     // W^T (K-major) splits
__device__ __nv_bfloat16 g_wt_lo[4ull*DIM*DIM];

// ----------------------------- PTX helpers ---------------------------------
__device__ __forceinline__ uint32_t smem_u32(const void* p) {
    uint32_t a;
    asm("{ .reg .u64 t; cvta.to.shared.u64 t, %1; cvt.u32.u64 %0, t; }"
        : "=r"(a) : "l"(p));
    return a;
}
__device__ __forceinline__ void cp_async16(uint32_t saddr, const void* g) {
    asm volatile("cp.async.cg.shared.global [%0], [%1], 16;"
                 :: "r"(saddr), "l"(g) : "memory");
}
__device__ __forceinline__ void cp_commit() {
    asm volatile("cp.async.commit_group;" ::: "memory");
}
template <int N>
__device__ __forceinline__ void cp_wait() {
    asm volatile("cp.async.wait_group %0;" :: "n"(N) : "memory");
}
// D += A(16x16 bf16, row) * B(16x8 bf16, col)   [f32 accum]
__device__ __forceinline__ void mma16816(float* c, const uint32_t* a,
                                         const uint32_t* b) {
    asm volatile(
        "mma.sync.aligned.m16n8k16.row.col.f32.bf16.bf16.f32 "
        "{%0,%1,%2,%3}, {%4,%5,%6,%7}, {%8,%9}, {%0,%1,%2,%3};"
        : "+f"(c[0]), "+f"(c[1]), "+f"(c[2]), "+f"(c[3])
        : "r"(a[0]), "r"(a[1]), "r"(a[2]), "r"(a[3]), "r"(b[0]), "r"(b[1]));
}

// ----------------------- split / transpose pre-passes ----------------------
__global__ void __launch_bounds__(256)
split_f32(const float* __restrict__ src, int which)
{
    const float* s = (which == 3) ? g_A : src;
    __nv_bfloat16* hi = (which == 3) ? g_a_hi : g_in_hi + (size_t)which * MTOT * DIM;
    __nv_bfloat16* lo = (which == 3) ? g_a_lo : g_in_lo + (size_t)which * MTOT * DIM;
    int i = blockIdx.x * 256 + threadIdx.x;        // over float4: 1M total
    float4 v = ((const float4*)s)[i];
    float xs[4] = {v.x, v.y, v.z, v.w};
    union { __nv_bfloat16 b[4]; uint2 u; } H, L;
    #pragma unroll
    for (int j = 0; j < 4; j++) {
        __nv_bfloat16 h = __float2bfloat16(xs[j]);
        H.b[j] = h;
        L.b[j] = __float2bfloat16(xs[j] - __bfloat162float(h));
    }
    ((uint2*)hi)[i] = H.u;
    ((uint2*)lo)[i] = L.u;
}

// Transpose W[k][n] -> Wt[n][k], split to bf16 hi/lo. grid (32,32,4), blk (32,8)
__global__ void __launch_bounds__(256)
wT_split(const float* __restrict__ wq, const float* __restrict__ wk,
         const float* __restrict__ wv, const float* __restrict__ wo)
{
    __shared__ float tile[32][33];
    const int z = blockIdx.z;
    const float* W = (z == 0) ? wq : (z == 1) ? wk : (z == 2) ? wv : wo;
    __nv_bfloat16* Hi = g_wt_hi + (size_t)z * DIM * DIM;
    __nv_bfloat16* Lo = g_wt_lo + (size_t)z * DIM * DIM;
    const int kb = blockIdx.x * 32, nb = blockIdx.y * 32;
    const int tx = threadIdx.x, ty = threadIdx.y;
    #pragma unroll
    for (int i = 0; i < 4; i++)
        tile[ty + i * 8][tx] = W[(size_t)(kb + ty + i * 8) * DIM + nb + tx];
    __syncthreads();
    #pragma unroll
    for (int i = 0; i < 4; i++) {
        float x = tile[tx][ty + i * 8];
        __nv_bfloat16 h = __float2bfloat16(x);
        __nv_bfloat16 l = __float2bfloat16(x - __bfloat162float(h));
        Hi[(size_t)(nb + ty + i * 8) * DIM + kb + tx] = h;
        Lo[(size_t)(nb + ty + i * 8) * DIM + kb + tx] = l;
    }
}

// ------------- mma.sync GEMM: C[4096,1024] = A @ Wt^T + bias ---------------
// Block 128x128, BK=32; 8 warps (2m x 4n), warp tile 64x32.
// SMEM per stage: Ahi/Alo/Bhi/Blo, each 128 rows x 32 bf16, row stride 40
// bf16 (80B -> conflict-free fragment LDS). 2 stages, cp.async pipeline.
#define GS_LDS   40                      // bf16 elements per smem row
#define GS_ROWB  (GS_LDS*2)              // 80 bytes
#define GS_ARR   (128*GS_ROWB)           // 10240 bytes per array
#define GS_AHI   0
#define GS_ALO   GS_ARR
#define GS_BHI   (2*GS_ARR)
#define GS_BLO   (3*GS_ARR)
#define GS_STAGE (4*GS_ARR)              // 40960
#define GEMM_SMEM (2*GS_STAGE)           // 81920

__device__ __forceinline__ void gemm_load_stage(
    char* smbase, uint32_t smu, int s, int c,
    const __nv_bfloat16* Ahi, const __nv_bfloat16* Alo,
    const __nv_bfloat16* Bhi, const __nv_bfloat16* Blo,
    int mBase, int nBase, int t)
{
    const uint32_t st = smu + s * GS_STAGE;
    #pragma unroll
    for (int it = 0; it < 2; it++) {
        int u = t + it * 256;
        int r = u >> 2, sec = u & 3;                 // row 0..127, 16B sector
        uint32_t so = (uint32_t)(r * GS_ROWB + sec * 16);
        size_t ga = ((size_t)(mBase + r) * DIM + c * 32 + sec * 8);
        size_t gb = ((size_t)(nBase + r) * DIM + c * 32 + sec * 8);
        cp_async16(st + GS_AHI + so, Ahi + ga);
        cp_async16(st + GS_ALO + so, Alo + ga);
        cp_async16(st + GS_BHI + so, Bhi + gb);
        cp_async16(st + GS_BLO + so, Blo + gb);
    }
}

__device__ void gemm_mma_tile(const __nv_bfloat16* __restrict__ Ahi,
                              const __nv_bfloat16* __restrict__ Alo,
                              const __nv_bfloat16* __restrict__ Bhi,
                              const __nv_bfloat16* __restrict__ Blo,
                              const float* __restrict__ bias,
                              float* __restrict__ C)
{
    extern __shared__ char smc[];
    const uint32_t smu = smem_u32(smc);
    const int t    = threadIdx.x;
    const int wid  = t >> 5, lane = t & 31;
    const int gid  = lane >> 2, tig = lane & 3;
    const int wm   = wid >> 2;                 // 0..1  (64 rows each)
    const int wn   = wid & 3;                  // 0..3  (32 cols each)
    const int mBase = blockIdx.y * 128;
    const int nBase = blockIdx.x * 128;

    float acc[4][4][4];
    #pragma unroll
    for (int i = 0; i < 4; i++)
        #pragma unroll
        for (int j = 0; j < 4; j++)
            #pragma unroll
            for (int q = 0; q < 4; q++) acc[i][j][q] = 0.0f;

    gemm_load_stage(smc, smu, 0, 0, Ahi, Alo, Bhi, Blo, mBase, nBase, t);
    cp_commit();

    const int NC = DIM / 32;   // 32 chunks
    for (int c = 0; c < NC; c++) {
        const int s = c & 1;
        if (c + 1 < NC) {
            gemm_load_stage(smc, smu, (c + 1) & 1, c + 1,
                            Ahi, Alo, Bhi, Blo, mBase, nBase, t);
            cp_commit();
            cp_wait<1>();
        } else {
            cp_wait<0>();
        }
        __syncthreads();

        const __nv_bfloat16* As  = (const __nv_bfloat16*)(smc + s*GS_STAGE + GS_AHI);
        const __nv_bfloat16* Asl = (const __nv_bfloat16*)(smc + s*GS_STAGE + GS_ALO);
        const __nv_bfloat16* Bs  = (const __nv_bfloat16*)(smc + s*GS_STAGE + GS_BHI);
        const __nv_bfloat16* Bsl = (const __nv_bfloat16*)(smc + s*GS_STAGE + GS_BLO);

        #pragma unroll
        for (int ks = 0; ks < 2; ks++) {
            const int kof = ks * 16;
            uint32_t ah[4][4], al[4][4], bh[4][2], bl[4][2];
            #pragma unroll
            for (int mi = 0; mi < 4; mi++) {
                const int r = wm * 64 + mi * 16 + gid;
                const int base = r * GS_LDS + kof + 2 * tig;
                ah[mi][0] = *(const uint32_t*)(As  + base);
                ah[mi][1] = *(const uint32_t*)(As  + base + 8 * GS_LDS);
                ah[mi][2] = *(const uint32_t*)(As  + base + 8);
                ah[mi][3] = *(const uint32_t*)(As  + base + 8 * GS_LDS + 8);
                al[mi][0] = *(const uint32_t*)(Asl + base);
                al[mi][1] = *(const uint32_t*)(Asl + base + 8 * GS_LDS);
                al[mi][2] = *(const uint32_t*)(Asl + base + 8);
                al[mi][3] = *(const uint32_t*)(Asl + base + 8 * GS_LDS + 8);
            }
            #pragma unroll
            for (int ni = 0; ni < 4; ni++) {
                const int n = wn * 32 + ni * 8 + gid;
                const int base = n * GS_LDS + kof + 2 * tig;
                bh[ni][0] = *(const uint32_t*)(Bs  + base);
                bh[ni][1] = *(const uint32_t*)(Bs  + base + 8);
                bl[ni][0] = *(const uint32_t*)(Bsl + base);
                bl[ni][1] = *(const uint32_t*)(Bsl + base + 8);
            }
            // hi*hi, then cross terms (16 independent accs between reuses)
            #pragma unroll
            for (int mi = 0; mi < 4; mi++)
                #pragma unroll
                for (int ni = 0; ni < 4; ni++)
                    mma16816(acc[mi][ni], ah[mi], bh[ni]);
            #pragma unroll
            for (int mi = 0; mi < 4; mi++)
                #pragma unroll
                for (int ni = 0; ni < 4; ni++)
                    mma16816(acc[mi][ni], ah[mi], bl[ni]);
            #pragma unroll
            for (int mi = 0; mi < 4; mi++)
                #pragma unroll
                for (int ni = 0; ni < 4; ni++)
                    mma16816(acc[mi][ni], al[mi], bh[ni]);
        }
        __syncthreads();
    }

    // Epilogue: c0,c1 -> (row, col..col+1); c2,c3 -> (row+8, ...)
    #pragma unroll
    for (int mi = 0; mi < 4; mi++) {
        const int row = mBase + wm * 64 + mi * 16 + gid;
        #pragma unroll
        for (int ni = 0; ni < 4; ni++) {
            const int col = nBase + wn * 32 + ni * 8 + 2 * tig;
            const float b0 = bias[col], b1 = bias[col + 1];
            float2 v01 = make_float2(acc[mi][ni][0] + b0, acc[mi][ni][1] + b1);
            float2 v23 = make_float2(acc[mi][ni][2] + b0, acc[mi][ni][3] + b1);
            *(float2*)(C + (size_t)row * DIM + col)       = v01;
            *(float2*)(C + (size_t)(row + 8) * DIM + col) = v23;
        }
    }
}

__global__ void __launch_bounds__(256, 1)
gemm_proj(const float* __restrict__ bq, const float* __restrict__ bk,
          const float* __restrict__ bv)
{
    const int z = blockIdx.z;
    const __nv_bfloat16* Ahi = g_in_hi + (size_t)z * MTOT * DIM;
    const __nv_bfloat16* Alo = g_in_lo + (size_t)z * MTOT * DIM;
    const __nv_bfloat16* Bhi = g_wt_hi + (size_t)z * DIM * DIM;
    const __nv_bfloat16* Blo = g_wt_lo + (size_t)z * DIM * DIM;
    const float* bias = (z == 0) ? bq : (z == 1) ? bk : bv;
    float* C = (z == 0) ? g_Q : (z == 1) ? g_K : g_V;
    gemm_mma_tile(Ahi, Alo, Bhi, Blo, bias, C);
}

__global__ void __launch_bounds__(256, 1)
gemm_out(const float* __restrict__ bo, float* __restrict__ out)
{
    gemm_mma_tile(g_a_hi, g_a_lo,
                  g_wt_hi + 3ull * DIM * DIM, g_wt_lo + 3ull * DIM * DIM,
                  bo, out);
}

// =================== Flash-style attention (unchanged, fp32) ================
#define Q_LD 68
#define K_LD 72
#define V_LD 68
#define P_LD 68
#define ATTN_SMEM_BYTES ((64*Q_LD + 64*K_LD + 64*V_LD + 64*P_LD) * 4) // 70656

__global__ void __launch_bounds__(256)
attn_kernel(const int* __restrict__ mask)
{
    extern __shared__ float sm[];
    float* Qs = sm;
    float* Kt = Qs + 64 * Q_LD;
    float* Vs = Kt + 64 * K_LD;
    float* Ps = Vs + 64 * V_LD;

    const int t  = threadIdx.x;
    const int b  = blockIdx.z;
    const int h  = blockIdx.y;
    const int q0 = blockIdx.x * 64;
    const int r0 = (t >> 4) * 4;
    const int c0 = (t & 15) * 4;

    const float* Qg = g_Q + ((size_t)b * SEQ + q0) * DIM + h * HDIM;
    const float* Kg = g_K + (size_t)b * SEQ * DIM + h * HDIM;
    const float* Vg = g_V + (size_t)b * SEQ * DIM + h * HDIM;

    #pragma unroll
    for (int i = 0; i < 4; i++) {
        int e = t + i * 256;
        int r = e >> 4, dq = e & 15;
        float4 v = *(const float4*)(Qg + r * DIM + dq * 4);
        *(float4*)&Qs[r * Q_LD + dq * 4] =
            make_float4(v.x * 0.125f, v.y * 0.125f, v.z * 0.125f, v.w * 0.125f);
    }

    float acc[4][4];
    #pragma unroll
    for (int i = 0; i < 4; i++)
        #pragma unroll
        for (int j = 0; j < 4; j++) acc[i][j] = 0.0f;
    float mrow[4] = {-1e30f, -1e30f, -1e30f, -1e30f};
    float lrow[4] = {0.0f, 0.0f, 0.0f, 0.0f};

    __syncthreads();

    for (int kt = 0; kt < SEQ / 64; kt++) {
        const int k0 = kt * 64;
        #pragma unroll
        for (int i = 0; i < 16; i++) {
            int e = t + i * 256;
            int kk = e >> 6, d = e & 63;
            Kt[d * K_LD + kk] = Kg[(size_t)(k0 + kk) * DIM + d];
        }
        #pragma unroll
        for (int i = 0; i < 4; i++) {
            int e = t + i * 256;
            int kk = e >> 4, dq = e & 15;
            *(float4*)&Vs[kk * V_LD + dq * 4] =
                *(const float4*)(Vg + (size_t)(k0 + kk) * DIM + dq * 4);
        }
        __syncthreads();

        float s[4][4];
        #pragma unroll
        for (int i = 0; i < 4; i++)
            #pragma unroll
            for (int j = 0; j < 4; j++) s[i][j] = 0.0f;
        #pragma unroll
        for (int d = 0; d < HDIM; d += 4) {
            float qv[4][4], kvf[4][4];
            #pragma unroll
            for (int i = 0; i < 4; i++) {
                float4 qq = *(const float4*)&Qs[(r0 + i) * Q_LD + d];
                qv[i][0] = qq.x; qv[i][1] = qq.y; qv[i][2] = qq.z; qv[i][3] = qq.w;
            }
            #pragma unroll
            for (int dd = 0; dd < 4; dd++) {
                float4 kk4 = *(const float4*)&Kt[(d + dd) * K_LD + c0];
                kvf[dd][0] = kk4.x; kvf[dd][1] = kk4.y; kvf[dd][2] = kk4.z; kvf[dd][3] = kk4.w;
            }
            #pragma unroll
            for (int i = 0; i < 4; i++)
                #pragma unroll
                for (int j = 0; j < 4; j++)
                    #pragma unroll
                    for (int dd = 0; dd < 4; dd++)
                        s[i][j] = fmaf(qv[i][dd], kvf[dd][j], s[i][j]);
        }

        #pragma unroll
        for (int i = 0; i < 4; i++) {
            const int4 mv = *(const int4*)(mask + (size_t)(q0 + r0 + i) * SEQ + k0 + c0);
            if (mv.x == 0) s[i][0] = -1e9f;
            if (mv.y == 0) s[i][1] = -1e9f;
            if (mv.z == 0) s[i][2] = -1e9f;
            if (mv.w == 0) s[i][3] = -1e9f;
            float tmax = fmaxf(fmaxf(s[i][0], s[i][1]), fmaxf(s[i][2], s[i][3]));
            #pragma unroll
            for (int o = 8; o > 0; o >>= 1)
                tmax = fmaxf(tmax, __shfl_xor_sync(0xffffffffu, tmax, o));
            const float newm  = fmaxf(mrow[i], tmax);
            const float scale = __expf(mrow[i] - newm);
            const float p0 = __expf(s[i][0] - newm);
            const float p1 = __expf(s[i][1] - newm);
            const float p2 = __expf(s[i][2] - newm);
            const float p3 = __expf(s[i][3] - newm);
            float tsum = p0 + p1 + p2 + p3;
            #pragma unroll
            for (int o = 8; o > 0; o >>= 1)
                tsum += __shfl_xor_sync(0xffffffffu, tsum, o);
            lrow[i] = lrow[i] * scale + tsum;
            mrow[i] = newm;
            acc[i][0] *= scale; acc[i][1] *= scale;
            acc[i][2] *= scale; acc[i][3] *= scale;
            *(float4*)&Ps[(r0 + i) * P_LD + c0] = make_float4(p0, p1, p2, p3);
        }
        __syncthreads();

        #pragma unroll
        for (int kk = 0; kk < 64; kk += 4) {
            float pv[4][4], vv[4][4];
            #pragma unroll
            for (int i = 0; i < 4; i++) {
                float4 pp = *(const float4*)&Ps[(r0 + i) * P_LD + kk];
                pv[i][0] = pp.x; pv[i][1] = pp.y; pv[i][2] = pp.z; pv[i][3] = pp.w;
            }
            #pragma unroll
            for (int kkk = 0; kkk < 4; kkk++) {
                float4 v4 = *(const float4*)&Vs[(kk + kkk) * V_LD + c0];
                vv[kkk][0] = v4.x; vv[kkk][1] = v4.y; vv[kkk][2] = v4.z; vv[kkk][3] = v4.w;
            }
            #pragma unroll
            for (int i = 0; i < 4; i++)
                #pragma unroll
                for (int j = 0; j < 4; j++)
                    #pragma unroll
                    for (int kkk = 0; kkk < 4; kkk++)
                        acc[i][j] = fmaf(pv[i][kkk], vv[kkk][j], acc[i][j]);
        }
        __syncthreads();
    }

    float* Og = g_A + ((size_t)b * SEQ + q0) * DIM + h * HDIM;
    #pragma unroll
    for (int i = 0; i < 4; i++) {
        const float inv = 1.0f / lrow[i];
        *(float4*)(Og + (size_t)(r0 + i) * DIM + c0) =
            make_float4(acc[i][0] * inv, acc[i][1] * inv,
                        acc[i][2] * inv, acc[i][3] * inv);
    }
}

// =============================== launch ====================================
extern "C" void kernel_launch(void* const* d_in, const int* in_sizes, int n_in,
                              void* d_out, int out_size)
{
    const float* q    = (const float*)d_in[0];
    const float* k    = (const float*)d_in[1];
    const float* v    = (const float*)d_in[2];
    const int*   mask = (const int*)  d_in[3];
    const float* w_q  = (const float*)d_in[4];
    const float* b_q  = (const float*)d_in[5];
    const float* w_k  = (const float*)d_in[6];
    const float* b_k  = (const float*)d_in[7];
    const float* w_v  = (const float*)d_in[8];
    const float* b_v  = (const float*)d_in[9];
    const float* w_o  = (const float*)d_in[10];
    const float* b_o  = (const float*)d_in[11];
    float* out = (float*)d_out;

    (void)in_sizes; (void)n_in; (void)out_size;

    cudaFuncSetAttribute(attn_kernel,
                         cudaFuncAttributeMaxDynamicSharedMemorySize,
                         ATTN_SMEM_BYTES);
    cudaFuncSetAttribute(gemm_proj,
                         cudaFuncAttributeMaxDynamicSharedMemorySize, GEMM_SMEM);
    cudaFuncSetAttribute(gemm_out,
                         cudaFuncAttributeMaxDynamicSharedMemorySize, GEMM_SMEM);

    // Pre-passes: weight transpose+split, input splits
    wT_split<<<dim3(32, 32, 4), dim3(32, 8)>>>(w_q, w_k, w_v, w_o);
    split_f32<<<4096, 256>>>(q, 0);
    split_f32<<<4096, 256>>>(k, 1);
    split_f32<<<4096, 256>>>(v, 2);

    // QKV projections on tensor cores (mma.sync bf16, split-compensated)
    gemm_proj<<<dim3(8, 32, 3), 256, GEMM_SMEM>>>(b_q, b_k, b_v);

    // Attention (fp32 SIMT)
    attn_kernel<<<dim3(SEQ / 64, NHEAD, BATCH), 256, ATTN_SMEM_BYTES>>>(mask);

    // Output projection on tensor cores
    split_f32<<<4096, 256>>>(nullptr, 3);
    gemm_out<<<dim3(8, 32), 256, GEMM_SMEM>>>(b_o, out);
}

// round 12
// speedup vs baseline: 2.2241x; 1.7198x over previous
#include <cuda_runtime.h>
#include <cuda_bf16.h>
#include <cstdint>

// ---------------------------------------------------------------------------
// MultiheadAttention: B=2, S=2048, D=1024, H=16, Dh=64
//   R12: attention moved to mma.sync bf16 3-split (same machinery as the
//   validated R11 GEMMs). Mask applied multiplicatively on P (softmax is
//   shift-invariant so row-max over the unmasked superset is exact).
//   Row sums via ones-column MMA. GEMMs unchanged from R11.
// ---------------------------------------------------------------------------

#define BATCH 2
#define SEQ   2048
#define DIM   1024
#define NHEAD 16
#define HDIM  64
#define MTOT  (BATCH*SEQ)   // 4096

// ----------------------------- device scratch ------------------------------
__device__ float g_Q[MTOT*DIM];
__device__ float g_K[MTOT*DIM];
__device__ float g_V[MTOT*DIM];
__device__ float g_A[MTOT*DIM];
__device__ __nv_bfloat16 g_in_hi[3ull*MTOT*DIM];   // split q,k,v inputs
__device__ __nv_bfloat16 g_in_lo[3ull*MTOT*DIM];
__device__ __nv_bfloat16 g_a_hi[MTOT*DIM];          // split attention output
__device__ __nv_bfloat16 g_a_lo[MTOT*DIM];
__device__ __nv_bfloat16 g_wt_hi[4ull*DIM*DIM];     // W^T (K-major) splits
__device__ __nv_bfloat16 g_wt_lo[4ull*DIM*DIM];
// attention operands
__device__ __nv_bfloat16 g_q_hi[MTOT*DIM];          // Q * 0.125*log2e, split
__device__ __nv_bfloat16 g_q_lo[MTOT*DIM];
__device__ __nv_bfloat16 g_k_hi[MTOT*DIM];
__device__ __nv_bfloat16 g_k_lo[MTOT*DIM];
__device__ __nv_bfloat16 g_vt_hi[(size_t)BATCH*NHEAD*HDIM*SEQ]; // V^T per head
__device__ __nv_bfloat16 g_vt_lo[(size_t)BATCH*NHEAD*HDIM*SEQ];
__device__ __nv_bfloat16 g_mfrag[(size_t)SEQ*SEQ];  // 0/1 bf16, frag-ordered

// ----------------------------- PTX helpers ---------------------------------
__device__ __forceinline__ uint32_t smem_u32(const void* p) {
    uint32_t a;
    asm("{ .reg .u64 t; cvta.to.shared.u64 t, %1; cvt.u32.u64 %0, t; }"
        : "=r"(a) : "l"(p));
    return a;
}
__device__ __forceinline__ void cp_async16(uint32_t saddr, const void* g) {
    asm volatile("cp.async.cg.shared.global [%0], [%1], 16;"
                 :: "r"(saddr), "l"(g) : "memory");
}
__device__ __forceinline__ void cp_commit() {
    asm volatile("cp.async.commit_group;" ::: "memory");
}
template <int N>
__device__ __forceinline__ void cp_wait() {
    asm volatile("cp.async.wait_group %0;" :: "n"(N) : "memory");
}
__device__ __forceinline__ void mma16816(float* c, const uint32_t* a,
                                         const uint32_t* b) {
    asm volatile(
        "mma.sync.aligned.m16n8k16.row.col.f32.bf16.bf16.f32 "
        "{%0,%1,%2,%3}, {%4,%5,%6,%7}, {%8,%9}, {%0,%1,%2,%3};"
        : "+f"(c[0]), "+f"(c[1]), "+f"(c[2]), "+f"(c[3])
        : "r"(a[0]), "r"(a[1]), "r"(a[2]), "r"(a[3]), "r"(b[0]), "r"(b[1]));
}
__device__ __forceinline__ float ex2f(float x) {
    float y; asm("ex2.approx.f32 %0, %1;" : "=f"(y) : "f"(x)); return y;
}
// pack two f32 -> bf16x2 (lo = first arg)
__device__ __forceinline__ uint32_t packbf(float lo, float hi) {
    uint32_t r;
    asm("cvt.rn.bf16x2.f32 %0, %1, %2;" : "=r"(r) : "f"(hi), "f"(lo));
    return r;
}

// ----------------------- split / transpose pre-passes ----------------------
__global__ void __launch_bounds__(256)
split_f32(const float* __restrict__ src, int which)
{
    const float* s = (which == 3) ? g_A : src;
    __nv_bfloat16* hi = (which == 3) ? g_a_hi : g_in_hi + (size_t)which * MTOT * DIM;
    __nv_bfloat16* lo = (which == 3) ? g_a_lo : g_in_lo + (size_t)which * MTOT * DIM;
    int i = blockIdx.x * 256 + threadIdx.x;
    float4 v = ((const float4*)s)[i];
    float xs[4] = {v.x, v.y, v.z, v.w};
    union { __nv_bfloat16 b[4]; uint2 u; } H, L;
    #pragma unroll
    for (int j = 0; j < 4; j++) {
        __nv_bfloat16 h = __float2bfloat16(xs[j]);
        H.b[j] = h;
        L.b[j] = __float2bfloat16(xs[j] - __bfloat162float(h));
    }
    ((uint2*)hi)[i] = H.u;
    ((uint2*)lo)[i] = L.u;
}

// split g_Q (scaled by 0.125*log2e) / g_K into bf16 hi/lo
__global__ void __launch_bounds__(256)
split_qk(int which)
{
    const float* s = which ? g_K : g_Q;
    __nv_bfloat16* hi = which ? g_k_hi : g_q_hi;
    __nv_bfloat16* lo = which ? g_k_lo : g_q_lo;
    const float sc = which ? 1.0f : 0.125f * 1.4426950408889634f;
    int i = blockIdx.x * 256 + threadIdx.x;
    float4 v = ((const float4*)s)[i];
    float xs[4] = {v.x * sc, v.y * sc, v.z * sc, v.w * sc};
    union { __nv_bfloat16 b[4]; uint2 u; } H, L;
    #pragma unroll
    for (int j = 0; j < 4; j++) {
        __nv_bfloat16 h = __float2bfloat16(xs[j]);
        H.b[j] = h;
        L.b[j] = __float2bfloat16(xs[j] - __bfloat162float(h));
    }
    ((uint2*)hi)[i] = H.u;
    ((uint2*)lo)[i] = L.u;
}

// g_V [b*S+s][h*64+d] -> g_vt[(b*16+h)*64+d][s], split hi/lo
__global__ void __launch_bounds__(256)
vt_split()
{
    __shared__ float tile[32][33];
    const int bh = blockIdx.z;                 // b*16+h
    const int s0 = blockIdx.x * 32, d0 = blockIdx.y * 32;
    const int b = bh >> 4, hh = bh & 15;
    const int tx = threadIdx.x, ty = threadIdx.y;
    #pragma unroll
    for (int i = 0; i < 4; i++)
        tile[ty + 8*i][tx] =
            g_V[(size_t)(b * SEQ + s0 + ty + 8*i) * DIM + hh * HDIM + d0 + tx];
    __syncthreads();
    #pragma unroll
    for (int i = 0; i < 4; i++) {
        float x = tile[tx][ty + 8*i];          // = V[s0+tx][d0+ty+8i]
        __nv_bfloat16 h = __float2bfloat16(x);
        __nv_bfloat16 l = __float2bfloat16(x - __bfloat162float(h));
        size_t o = (size_t)(bh * HDIM + d0 + ty + 8*i) * SEQ + s0 + tx;
        g_vt_hi[o] = h;
        g_vt_lo[o] = l;
    }
}

// mask int32 [2048][2048] -> bf16 0/1 in exact per-thread fragment order.
// word index Wd: tile = Wd>>12 (qt=tile>>5, kt=tile&31); tid = (Wd&4095)>>4;
// j = Wd&15: ni = j>>1, rowhalf = j&1.
__global__ void __launch_bounds__(256)
mask_frag(const int* __restrict__ mask)
{
    int Wd = blockIdx.x * 256 + threadIdx.x;   // 0 .. 2M-1
    int tile = Wd >> 12;
    int qt = tile >> 5, kt = tile & 31;
    int rem = Wd & 4095;
    int tid = rem >> 4, j = rem & 15;
    int w = tid >> 5, lane = tid & 31;
    int gid = lane >> 2, tig = lane & 3;
    int ni = j >> 1, rh = j & 1;
    int row = qt * 128 + w * 16 + gid + rh * 8;
    int col = kt * 64 + ni * 8 + tig * 2;
    int m0 = mask[(size_t)row * SEQ + col];
    int m1 = mask[(size_t)row * SEQ + col + 1];
    uint32_t v = (m0 ? 0x3F80u : 0u) | (m1 ? (0x3F80u << 16) : 0u);
    ((uint32_t*)g_mfrag)[Wd] = v;
}

// Transpose W[k][n] -> Wt[n][k], split to bf16 hi/lo. grid (32,32,4), blk (32,8)
__global__ void __launch_bounds__(256)
wT_split(const float* __restrict__ wq, const float* __restrict__ wk,
         const float* __restrict__ wv, const float* __restrict__ wo)
{
    __shared__ float tile[32][33];
    const int z = blockIdx.z;
    const float* W = (z == 0) ? wq : (z == 1) ? wk : (z == 2) ? wv : wo;
    __nv_bfloat16* Hi = g_wt_hi + (size_t)z * DIM * DIM;
    __nv_bfloat16* Lo = g_wt_lo + (size_t)z * DIM * DIM;
    const int kb = blockIdx.x * 32, nb = blockIdx.y * 32;
    const int tx = threadIdx.x, ty = threadIdx.y;
    #pragma unroll
    for (int i = 0; i < 4; i++)
        tile[ty + i * 8][tx] = W[(size_t)(kb + ty + i * 8) * DIM + nb + tx];
    __syncthreads();
    #pragma unroll
    for (int i = 0; i < 4; i++) {
        float x = tile[tx][ty + i * 8];
        __nv_bfloat16 h = __float2bfloat16(x);
        __nv_bfloat16 l = __float2bfloat16(x - __bfloat162float(h));
        Hi[(size_t)(nb + ty + i * 8) * DIM + kb + tx] = h;
        Lo[(size_t)(nb + ty + i * 8) * DIM + kb + tx] = l;
    }
}

// ------------- mma.sync GEMM (unchanged from R11, validated) ---------------
#define GS_LDS   40
#define GS_ROWB  (GS_LDS*2)
#define GS_ARR   (128*GS_ROWB)
#define GS_AHI   0
#define GS_ALO   GS_ARR
#define GS_BHI   (2*GS_ARR)
#define GS_BLO   (3*GS_ARR)
#define GS_STAGE (4*GS_ARR)
#define GEMM_SMEM (2*GS_STAGE)

__device__ __forceinline__ void gemm_load_stage(
    char* smbase, uint32_t smu, int s, int c,
    const __nv_bfloat16* Ahi, const __nv_bfloat16* Alo,
    const __nv_bfloat16* Bhi, const __nv_bfloat16* Blo,
    int mBase, int nBase, int t)
{
    const uint32_t st = smu + s * GS_STAGE;
    #pragma unroll
    for (int it = 0; it < 2; it++) {
        int u = t + it * 256;
        int r = u >> 2, sec = u & 3;
        uint32_t so = (uint32_t)(r * GS_ROWB + sec * 16);
        size_t ga = ((size_t)(mBase + r) * DIM + c * 32 + sec * 8);
        size_t gb = ((size_t)(nBase + r) * DIM + c * 32 + sec * 8);
        cp_async16(st + GS_AHI + so, Ahi + ga);
        cp_async16(st + GS_ALO + so, Alo + ga);
        cp_async16(st + GS_BHI + so, Bhi + gb);
        cp_async16(st + GS_BLO + so, Blo + gb);
    }
}

__device__ void gemm_mma_tile(const __nv_bfloat16* __restrict__ Ahi,
                              const __nv_bfloat16* __restrict__ Alo,
                              const __nv_bfloat16* __restrict__ Bhi,
                              const __nv_bfloat16* __restrict__ Blo,
                              const float* __restrict__ bias,
                              float* __restrict__ C)
{
    extern __shared__ char smc[];
    const uint32_t smu = smem_u32(smc);
    const int t    = threadIdx.x;
    const int wid  = t >> 5, lane = t & 31;
    const int gid  = lane >> 2, tig = lane & 3;
    const int wm   = wid >> 2;
    const int wn   = wid & 3;
    const int mBase = blockIdx.y * 128;
    const int nBase = blockIdx.x * 128;

    float acc[4][4][4];
    #pragma unroll
    for (int i = 0; i < 4; i++)
        #pragma unroll
        for (int j = 0; j < 4; j++)
            #pragma unroll
            for (int q = 0; q < 4; q++) acc[i][j][q] = 0.0f;

    gemm_load_stage(smc, smu, 0, 0, Ahi, Alo, Bhi, Blo, mBase, nBase, t);
    cp_commit();

    const int NC = DIM / 32;
    for (int c = 0; c < NC; c++) {
        const int s = c & 1;
        if (c + 1 < NC) {
            gemm_load_stage(smc, smu, (c + 1) & 1, c + 1,
                            Ahi, Alo, Bhi, Blo, mBase, nBase, t);
            cp_commit();
            cp_wait<1>();
        } else {
            cp_wait<0>();
        }
        __syncthreads();

        const __nv_bfloat16* As  = (const __nv_bfloat16*)(smc + s*GS_STAGE + GS_AHI);
        const __nv_bfloat16* Asl = (const __nv_bfloat16*)(smc + s*GS_STAGE + GS_ALO);
        const __nv_bfloat16* Bs  = (const __nv_bfloat16*)(smc + s*GS_STAGE + GS_BHI);
        const __nv_bfloat16* Bsl = (const __nv_bfloat16*)(smc + s*GS_STAGE + GS_BLO);

        #pragma unroll
        for (int ks = 0; ks < 2; ks++) {
            const int kof = ks * 16;
            uint32_t ah[4][4], al[4][4], bh[4][2], bl[4][2];
            #pragma unroll
            for (int mi = 0; mi < 4; mi++) {
                const int r = wm * 64 + mi * 16 + gid;
                const int base = r * GS_LDS + kof + 2 * tig;
                ah[mi][0] = *(const uint32_t*)(As  + base);
                ah[mi][1] = *(const uint32_t*)(As  + base + 8 * GS_LDS);
                ah[mi][2] = *(const uint32_t*)(As  + base + 8);
                ah[mi][3] = *(const uint32_t*)(As  + base + 8 * GS_LDS + 8);
                al[mi][0] = *(const uint32_t*)(Asl + base);
                al[mi][1] = *(const uint32_t*)(Asl + base + 8 * GS_LDS);
                al[mi][2] = *(const uint32_t*)(Asl + base + 8);
                al[mi][3] = *(const uint32_t*)(Asl + base + 8 * GS_LDS + 8);
            }
            #pragma unroll
            for (int ni = 0; ni < 4; ni++) {
                const int n = wn * 32 + ni * 8 + gid;
                const int base = n * GS_LDS + kof + 2 * tig;
                bh[ni][0] = *(const uint32_t*)(Bs  + base);
                bh[ni][1] = *(const uint32_t*)(Bs  + base + 8);
                bl[ni][0] = *(const uint32_t*)(Bsl + base);
                bl[ni][1] = *(const uint32_t*)(Bsl + base + 8);
            }
            #pragma unroll
            for (int mi = 0; mi < 4; mi++)
                #pragma unroll
                for (int ni = 0; ni < 4; ni++)
                    mma16816(acc[mi][ni], ah[mi], bh[ni]);
            #pragma unroll
            for (int mi = 0; mi < 4; mi++)
                #pragma unroll
                for (int ni = 0; ni < 4; ni++)
                    mma16816(acc[mi][ni], ah[mi], bl[ni]);
            #pragma unroll
            for (int mi = 0; mi < 4; mi++)
                #pragma unroll
                for (int ni = 0; ni < 4; ni++)
                    mma16816(acc[mi][ni], al[mi], bh[ni]);
        }
        __syncthreads();
    }

    #pragma unroll
    for (int mi = 0; mi < 4; mi++) {
        const int row = mBase + wm * 64 + mi * 16 + gid;
        #pragma unroll
        for (int ni = 0; ni < 4; ni++) {
            const int col = nBase + wn * 32 + ni * 8 + 2 * tig;
            const float b0 = bias[col], b1 = bias[col + 1];
            float2 v01 = make_float2(acc[mi][ni][0] + b0, acc[mi][ni][1] + b1);
            float2 v23 = make_float2(acc[mi][ni][2] + b0, acc[mi][ni][3] + b1);
            *(float2*)(C + (size_t)row * DIM + col)       = v01;
            *(float2*)(C + (size_t)(row + 8) * DIM + col) = v23;
        }
    }
}

__global__ void __launch_bounds__(256, 1)
gemm_proj(const float* __restrict__ bq, const float* __restrict__ bk,
          const float* __restrict__ bv)
{
    const int z = blockIdx.z;
    const __nv_bfloat16* Ahi = g_in_hi + (size_t)z * MTOT * DIM;
    const __nv_bfloat16* Alo = g_in_lo + (size_t)z * MTOT * DIM;
    const __nv_bfloat16* Bhi = g_wt_hi + (size_t)z * DIM * DIM;
    const __nv_bfloat16* Blo = g_wt_lo + (size_t)z * DIM * DIM;
    const float* bias = (z == 0) ? bq : (z == 1) ? bk : bv;
    float* C = (z == 0) ? g_Q : (z == 1) ? g_K : g_V;
    gemm_mma_tile(Ahi, Alo, Bhi, Blo, bias, C);
}

__global__ void __launch_bounds__(256, 1)
gemm_out(const float* __restrict__ bo, float* __restrict__ out)
{
    gemm_mma_tile(g_a_hi, g_a_lo,
                  g_wt_hi + 3ull * DIM * DIM, g_wt_lo + 3ull * DIM * DIM,
                  bo, out);
}

// ==================== attention on mma.sync (flash) =========================
// CTA: 128 q-rows, 8 warps x 16 rows. k-tiles of 64. 2-stage cp.async.
// smem rows padded to 72 bf16 (144 B) -> conflict-free fragment loads.
#define A_LD   72
#define AQ_HI  0
#define AQ_LO  18432
#define AST0   36864
#define AK_HI  0
#define AK_LO  9216
#define AV_HI  18432
#define AV_LO  27648
#define AMSK   36864
#define AST_SZ 53248
#define ATTN_SMEM (AST0 + 2*AST_SZ)   // 143360

__device__ __forceinline__ void attn_load_stage(uint32_t sb, int s, int kt,
                                                int bb, int hh, int bh,
                                                int qt, int t)
{
    const uint32_t st = sb + AST0 + s * AST_SZ;
    #pragma unroll
    for (int it = 0; it < 4; ++it) {
        int u = t + it * 256;
        int sp = u >> 9, r = (u >> 3) & 63, sec = u & 7;
        const __nv_bfloat16* ks = (sp ? g_k_lo : g_k_hi)
            + ((size_t)(bb * SEQ + kt * 64 + r) * DIM + hh * HDIM + sec * 8);
        cp_async16(st + (sp ? AK_LO : AK_HI) + r * 144 + sec * 16, ks);
        const __nv_bfloat16* vs = (sp ? g_vt_lo : g_vt_hi)
            + ((size_t)(bh * HDIM + r) * SEQ + kt * 64 + sec * 8);
        cp_async16(st + (sp ? AV_LO : AV_HI) + r * 144 + sec * 16, vs);
    }
    const __nv_bfloat16* ms = g_mfrag + ((size_t)(qt * 32 + kt) * 8192) + t * 32;
    #pragma unroll
    for (int c = 0; c < 4; ++c)
        cp_async16(st + AMSK + t * 64 + c * 16, ms + c * 8);
}

__global__ void __launch_bounds__(256)
attn_mma()
{
    extern __shared__ char sm[];
    const uint32_t sb = smem_u32(sm);
    const int t = threadIdx.x, w = t >> 5, lane = t & 31;
    const int gid = lane >> 2, tig = lane & 3;
    const int qt = blockIdx.x, hh = blockIdx.y, bb = blockIdx.z;
    const int q0 = qt * 128;
    const int bh = bb * NHEAD + hh;

    // Q tile (hi/lo), resident for whole kernel
    #pragma unroll
    for (int it = 0; it < 8; ++it) {
        int u = t + it * 256;
        int sp = u >> 10, r = (u >> 3) & 127, sec = u & 7;
        const __nv_bfloat16* src = (sp ? g_q_lo : g_q_hi)
            + ((size_t)(bb * SEQ + q0 + r) * DIM + hh * HDIM + sec * 8);
        cp_async16(sb + (sp ? AQ_LO : AQ_HI) + r * 144 + sec * 16, src);
    }
    attn_load_stage(sb, 0, 0, bb, hh, bh, qt, t);
    cp_commit();

    float oacc[8][4];
    #pragma unroll
    for (int i = 0; i < 8; i++)
        #pragma unroll
        for (int j = 0; j < 4; j++) oacc[i][j] = 0.0f;
    float lacc[4] = {0.0f, 0.0f, 0.0f, 0.0f};
    float m0 = -1e30f, m1 = -1e30f;

    const __nv_bfloat16* Qh = (const __nv_bfloat16*)(sm + AQ_HI);
    const __nv_bfloat16* Ql = (const __nv_bfloat16*)(sm + AQ_LO);
    const int arow = (w * 16 + gid) * A_LD;

    for (int kt = 0; kt < SEQ / 64; ++kt) {
        if (kt + 1 < SEQ / 64) {
            attn_load_stage(sb, (kt + 1) & 1, kt + 1, bb, hh, bh, qt, t);
            cp_commit();
            cp_wait<1>();
        } else {
            cp_wait<0>();
        }
        __syncthreads();

        const char* stp = sm + AST0 + (kt & 1) * AST_SZ;
        const __nv_bfloat16* Kh = (const __nv_bfloat16*)(stp + AK_HI);
        const __nv_bfloat16* Kl = (const __nv_bfloat16*)(stp + AK_LO);
        const __nv_bfloat16* Vh = (const __nv_bfloat16*)(stp + AV_HI);
        const __nv_bfloat16* Vl = (const __nv_bfloat16*)(stp + AV_LO);
        const uint32_t* Mw = (const uint32_t*)(stp + AMSK) + t * 16;

        // ---- S = Q K^T (3-split), 128x64 per CTA, 16x64 per warp ----
        float sacc[8][4];
        #pragma unroll
        for (int i = 0; i < 8; i++)
            #pragma unroll
            for (int j = 0; j < 4; j++) sacc[i][j] = 0.0f;

        #pragma unroll
        for (int kp = 0; kp < 4; ++kp) {
            const int ab = arow + kp * 16 + 2 * tig;
            uint32_t ah[4] = {
                *(const uint32_t*)(Qh + ab),
                *(const uint32_t*)(Qh + ab + 8 * A_LD),
                *(const uint32_t*)(Qh + ab + 8),
                *(const uint32_t*)(Qh + ab + 8 * A_LD + 8) };
            uint32_t al[4] = {
                *(const uint32_t*)(Ql + ab),
                *(const uint32_t*)(Ql + ab + 8 * A_LD),
                *(const uint32_t*)(Ql + ab + 8),
                *(const uint32_t*)(Ql + ab + 8 * A_LD + 8) };
            #pragma unroll
            for (int ni = 0; ni < 8; ++ni) {
                const int bbse = (ni * 8 + gid) * A_LD + kp * 16 + 2 * tig;
                uint32_t bhf[2] = { *(const uint32_t*)(Kh + bbse),
                                    *(const uint32_t*)(Kh + bbse + 8) };
                uint32_t blf[2] = { *(const uint32_t*)(Kl + bbse),
                                    *(const uint32_t*)(Kl + bbse + 8) };
                mma16816(sacc[ni], ah, bhf);
                mma16816(sacc[ni], ah, blf);
                mma16816(sacc[ni], al, bhf);
            }
        }

        // ---- online softmax (scores already in log2 units) ----
        float t0 = sacc[0][0], t1 = sacc[0][2];
        #pragma unroll
        for (int ni = 0; ni < 8; ++ni) {
            t0 = fmaxf(t0, fmaxf(sacc[ni][0], sacc[ni][1]));
            t1 = fmaxf(t1, fmaxf(sacc[ni][2], sacc[ni][3]));
        }
        t0 = fmaxf(t0, __shfl_xor_sync(0xffffffffu, t0, 1));
        t0 = fmaxf(t0, __shfl_xor_sync(0xffffffffu, t0, 2));
        t1 = fmaxf(t1, __shfl_xor_sync(0xffffffffu, t1, 1));
        t1 = fmaxf(t1, __shfl_xor_sync(0xffffffffu, t1, 2));
        const float nm0 = fmaxf(m0, t0), nm1 = fmaxf(m1, t1);
        const float f0 = ex2f(m0 - nm0), f1 = ex2f(m1 - nm1);
        m0 = nm0; m1 = nm1;
        #pragma unroll
        for (int ni = 0; ni < 8; ++ni) {
            oacc[ni][0] *= f0; oacc[ni][1] *= f0;
            oacc[ni][2] *= f1; oacc[ni][3] *= f1;
        }
        lacc[0] *= f0; lacc[1] *= f0; lacc[2] *= f1; lacc[3] *= f1;

        // ---- p = exp2(s - m), mask multiply (0/1), hi/lo pack ----
        uint32_t PH[8][2], PL[8][2];
        #pragma unroll
        for (int ni = 0; ni < 8; ++ni) {
            float p0 = ex2f(sacc[ni][0] - nm0);
            float p1 = ex2f(sacc[ni][1] - nm0);
            float p2 = ex2f(sacc[ni][2] - nm1);
            float p3 = ex2f(sacc[ni][3] - nm1);
            const uint32_t w0 = Mw[2 * ni], w1 = Mw[2 * ni + 1];
            p0 *= __uint_as_float(w0 << 16);
            p1 *= __uint_as_float(w0 & 0xFFFF0000u);
            p2 *= __uint_as_float(w1 << 16);
            p3 *= __uint_as_float(w1 & 0xFFFF0000u);
            const uint32_t h0 = packbf(p0, p1);
            const uint32_t h1 = packbf(p2, p3);
            const float r0 = p0 - __uint_as_float(h0 << 16);
            const float r1 = p1 - __uint_as_float(h0 & 0xFFFF0000u);
            const float r2 = p2 - __uint_as_float(h1 << 16);
            const float r3 = p3 - __uint_as_float(h1 & 0xFFFF0000u);
            PH[ni][0] = h0; PH[ni][1] = h1;
            PL[ni][0] = packbf(r0, r1);
            PL[ni][1] = packbf(r2, r3);
        }

        // ---- O += P V (3-split); l += P . ones ----
        const uint32_t ones[2] = {0x3F803F80u, 0x3F803F80u};
        #pragma unroll
        for (int kp = 0; kp < 4; ++kp) {
            uint32_t aph[4] = { PH[2*kp][0], PH[2*kp][1],
                                PH[2*kp+1][0], PH[2*kp+1][1] };
            uint32_t apl[4] = { PL[2*kp][0], PL[2*kp][1],
                                PL[2*kp+1][0], PL[2*kp+1][1] };
            mma16816(lacc, aph, ones);
            mma16816(lacc, apl, ones);
            #pragma unroll
            for (int ni = 0; ni < 8; ++ni) {
                const int vb = (ni * 8 + gid) * A_LD + kp * 16 + 2 * tig;
                uint32_t bh2[2] = { *(const uint32_t*)(Vh + vb),
                                    *(const uint32_t*)(Vh + vb + 8) };
                uint32_t bl2[2] = { *(const uint32_t*)(Vl + vb),
                                    *(const uint32_t*)(Vl + vb + 8) };
                mma16816(oacc[ni], aph, bh2);
                mma16816(oacc[ni], aph, bl2);
                mma16816(oacc[ni], apl, bh2);
            }
        }
        __syncthreads();
    }

    // ---- normalize + write g_A [b*S+q][h*64+d] ----
    const float inv0 = 1.0f / lacc[0];
    const float inv1 = 1.0f / lacc[2];
    float* O0 = g_A + (size_t)(bb * SEQ + q0 + w * 16 + gid) * DIM + hh * HDIM;
    float* O1 = O0 + 8 * DIM;
    #pragma unroll
    for (int ni = 0; ni < 8; ++ni) {
        const int col = ni * 8 + 2 * tig;
        *(float2*)(O0 + col) = make_float2(oacc[ni][0] * inv0, oacc[ni][1] * inv0);
        *(float2*)(O1 + col) = make_float2(oacc[ni][2] * inv1, oacc[ni][3] * inv1);
    }
}

// =============================== launch ====================================
extern "C" void kernel_launch(void* const* d_in, const int* in_sizes, int n_in,
                              void* d_out, int out_size)
{
    const float* q    = (const float*)d_in[0];
    const float* k    = (const float*)d_in[1];
    const float* v    = (const float*)d_in[2];
    const int*   mask = (const int*)  d_in[3];
    const float* w_q  = (const float*)d_in[4];
    const float* b_q  = (const float*)d_in[5];
    const float* w_k  = (const float*)d_in[6];
    const float* b_k  = (const float*)d_in[7];
    const float* w_v  = (const float*)d_in[8];
    const float* b_v  = (const float*)d_in[9];
    const float* w_o  = (const float*)d_in[10];
    const float* b_o  = (const float*)d_in[11];
    float* out = (float*)d_out;

    (void)in_sizes; (void)n_in; (void)out_size;

    cudaFuncSetAttribute(gemm_proj,
                         cudaFuncAttributeMaxDynamicSharedMemorySize, GEMM_SMEM);
    cudaFuncSetAttribute(gemm_out,
                         cudaFuncAttributeMaxDynamicSharedMemorySize, GEMM_SMEM);
    cudaFuncSetAttribute(attn_mma,
                         cudaFuncAttributeMaxDynamicSharedMemorySize, ATTN_SMEM);

    // Pre-passes
    wT_split<<<dim3(32, 32, 4), dim3(32, 8)>>>(w_q, w_k, w_v, w_o);
    split_f32<<<4096, 256>>>(q, 0);
    split_f32<<<4096, 256>>>(k, 1);
    split_f32<<<4096, 256>>>(v, 2);
    mask_frag<<<(SEQ * SEQ / 2) / 256, 256>>>(mask);

    // QKV projections (tensor cores)
    gemm_proj<<<dim3(8, 32, 3), 256, GEMM_SMEM>>>(b_q, b_k, b_v);

    // Attention operand prep
    split_qk<<<4096, 256>>>(0);
    split_qk<<<4096, 256>>>(1);
    vt_split<<<dim3(SEQ / 32, HDIM / 32, BATCH * NHEAD), dim3(32, 8)>>>();

    // Attention (tensor cores, flash)
    attn_mma<<<dim3(SEQ / 128, NHEAD, BATCH), 256, ATTN_SMEM>>>();

    // Output projection (tensor cores)
    split_f32<<<4096, 256>>>(nullptr, 3);
    gemm_out<<<dim3(8, 32), 256, GEMM_SMEM>>>(b_o, out);
}

// round 14
// speedup vs baseline: 2.3782x; 1.0693x over previous
#include <cuda_runtime.h>
#include <cuda_bf16.h>
#include <cuda_fp16.h>
#include <cstdint>

// ---------------------------------------------------------------------------
// MultiheadAttention: B=2, S=2048, D=1024, H=16, Dh=64
//   R14 (= R13 resubmit after infra failure):
//   (1) split pre-passes fused into GEMM/attn epilogues (Q/K written as
//   scaled bf16 hi/lo straight from the projection; attn output written as
//   bf16 hi/lo). (2) PV product on fp16: P single (error cancels in O/l
//   normalization), V 2-split fp16 -> 2 MMAs instead of 3; l-sum 1 MMA.
//   QK^T stays bf16 3-split (exp is abs-error sensitive). GEMM core from R11.
// ---------------------------------------------------------------------------

#define BATCH 2
#define SEQ   2048
#define DIM   1024
#define NHEAD 16
#define HDIM  64
#define MTOT  (BATCH*SEQ)   // 4096

// ----------------------------- device scratch ------------------------------
__device__ float g_V[MTOT*DIM];                     // fp32 V (for vt_split)
__device__ __nv_bfloat16 g_in_hi[3ull*MTOT*DIM];    // split q,k,v inputs
__device__ __nv_bfloat16 g_in_lo[3ull*MTOT*DIM];
__device__ __nv_bfloat16 g_a_hi[MTOT*DIM];          // attn output (split)
__device__ __nv_bfloat16 g_a_lo[MTOT*DIM];
__device__ __nv_bfloat16 g_wt_hi[4ull*DIM*DIM];     // W^T (K-major) splits
__device__ __nv_bfloat16 g_wt_lo[4ull*DIM*DIM];
__device__ __nv_bfloat16 g_q_hi[MTOT*DIM];          // Q * 0.125*log2e, split
__device__ __nv_bfloat16 g_q_lo[MTOT*DIM];
__device__ __nv_bfloat16 g_k_hi[MTOT*DIM];
__device__ __nv_bfloat16 g_k_lo[MTOT*DIM];
__device__ __half g_vt_hi[(size_t)BATCH*NHEAD*HDIM*SEQ];  // V^T fp16 splits
__device__ __half g_vt_lo[(size_t)BATCH*NHEAD*HDIM*SEQ];
__device__ __nv_bfloat16 g_mfrag[(size_t)SEQ*SEQ];  // 0/1 bf16, frag-ordered

// ----------------------------- PTX helpers ---------------------------------
__device__ __forceinline__ uint32_t smem_u32(const void* p) {
    uint32_t a;
    asm("{ .reg .u64 t; cvta.to.shared.u64 t, %1; cvt.u32.u64 %0, t; }"
        : "=r"(a) : "l"(p));
    return a;
}
__device__ __forceinline__ void cp_async16(uint32_t saddr, const void* g) {
    asm volatile("cp.async.cg.shared.global [%0], [%1], 16;"
                 :: "r"(saddr), "l"(g) : "memory");
}
__device__ __forceinline__ void cp_commit() {
    asm volatile("cp.async.commit_group;" ::: "memory");
}
template <int N>
__device__ __forceinline__ void cp_wait() {
    asm volatile("cp.async.wait_group %0;" :: "n"(N) : "memory");
}
__device__ __forceinline__ void mma16816(float* c, const uint32_t* a,
                                         const uint32_t* b) {
    asm volatile(
        "mma.sync.aligned.m16n8k16.row.col.f32.bf16.bf16.f32 "
        "{%0,%1,%2,%3}, {%4,%5,%6,%7}, {%8,%9}, {%0,%1,%2,%3};"
        : "+f"(c[0]), "+f"(c[1]), "+f"(c[2]), "+f"(c[3])
        : "r"(a[0]), "r"(a[1]), "r"(a[2]), "r"(a[3]), "r"(b[0]), "r"(b[1]));
}
__device__ __forceinline__ void mma16816h(float* c, const uint32_t* a,
                                          const uint32_t* b) {
    asm volatile(
        "mma.sync.aligned.m16n8k16.row.col.f32.f16.f16.f32 "
        "{%0,%1,%2,%3}, {%4,%5,%6,%7}, {%8,%9}, {%0,%1,%2,%3};"
        : "+f"(c[0]), "+f"(c[1]), "+f"(c[2]), "+f"(c[3])
        : "r"(a[0]), "r"(a[1]), "r"(a[2]), "r"(a[3]), "r"(b[0]), "r"(b[1]));
}
__device__ __forceinline__ float ex2f(float x) {
    float y; asm("ex2.approx.f32 %0, %1;" : "=f"(y) : "f"(x)); return y;
}
// pack two f32 -> f16x2 (first arg lands in the low half)
__device__ __forceinline__ uint32_t packh(float lo, float hi) {
    uint32_t r;
    asm("cvt.rn.f16x2.f32 %0, %1, %2;" : "=r"(r) : "f"(hi), "f"(lo));
    return r;
}

// ----------------------- split / transpose pre-passes ----------------------
__global__ void __launch_bounds__(256)
split_f32(const float* __restrict__ src, int which)
{
    __nv_bfloat16* hi = g_in_hi + (size_t)which * MTOT * DIM;
    __nv_bfloat16* lo = g_in_lo + (size_t)which * MTOT * DIM;
    int i = blockIdx.x * 256 + threadIdx.x;
    float4 v = ((const float4*)src)[i];
    float xs[4] = {v.x, v.y, v.z, v.w};
    union { __nv_bfloat16 b[4]; uint2 u; } H, L;
    #pragma unroll
    for (int j = 0; j < 4; j++) {
        __nv_bfloat16 h = __float2bfloat16(xs[j]);
        H.b[j] = h;
        L.b[j] = __float2bfloat16(xs[j] - __bfloat162float(h));
    }
    ((uint2*)hi)[i] = H.u;
    ((uint2*)lo)[i] = L.u;
}

// g_V [b*S+s][h*64+d] -> g_vt[(b*16+h)*64+d][s], fp16 2-split
__global__ void __launch_bounds__(256)
vt_split()
{
    __shared__ float tile[32][33];
    const int bh = blockIdx.z;
    const int s0 = blockIdx.x * 32, d0 = blockIdx.y * 32;
    const int b = bh >> 4, hh = bh & 15;
    const int tx = threadIdx.x, ty = threadIdx.y;
    #pragma unroll
    for (int i = 0; i < 4; i++)
        tile[ty + 8*i][tx] =
            g_V[(size_t)(b * SEQ + s0 + ty + 8*i) * DIM + hh * HDIM + d0 + tx];
    __syncthreads();
    #pragma unroll
    for (int i = 0; i < 4; i++) {
        float x = tile[tx][ty + 8*i];
        __half h = __float2half(x);
        __half l = __float2half(x - __half2float(h));
        size_t o = (size_t)(bh * HDIM + d0 + ty + 8*i) * SEQ + s0 + tx;
        g_vt_hi[o] = h;
        g_vt_lo[o] = l;
    }
}

// mask int32 -> bf16 0/1 in exact per-thread fragment order (validated R12)
__global__ void __launch_bounds__(256)
mask_frag(const int* __restrict__ mask)
{
    int Wd = blockIdx.x * 256 + threadIdx.x;
    int tile = Wd >> 12;
    int qt = tile >> 5, kt = tile & 31;
    int rem = Wd & 4095;
    int tid = rem >> 4, j = rem & 15;
    int w = tid >> 5, lane = tid & 31;
    int gid = lane >> 2, tig = lane & 3;
    int ni = j >> 1, rh = j & 1;
    int row = qt * 128 + w * 16 + gid + rh * 8;
    int col = kt * 64 + ni * 8 + tig * 2;
    int m0 = mask[(size_t)row * SEQ + col];
    int m1 = mask[(size_t)row * SEQ + col + 1];
    uint32_t v = (m0 ? 0x3F80u : 0u) | (m1 ? (0x3F80u << 16) : 0u);
    ((uint32_t*)g_mfrag)[Wd] = v;
}

// Transpose W[k][n] -> Wt[n][k], split to bf16 hi/lo. grid (32,32,4), blk (32,8)
__global__ void __launch_bounds__(256)
wT_split(const float* __restrict__ wq, const float* __restrict__ wk,
         const float* __restrict__ wv, const float* __restrict__ wo)
{
    __shared__ float tile[32][33];
    const int z = blockIdx.z;
    const float* W = (z == 0) ? wq : (z == 1) ? wk : (z == 2) ? wv : wo;
    __nv_bfloat16* Hi = g_wt_hi + (size_t)z * DIM * DIM;
    __nv_bfloat16* Lo = g_wt_lo + (size_t)z * DIM * DIM;
    const int kb = blockIdx.x * 32, nb = blockIdx.y * 32;
    const int tx = threadIdx.x, ty = threadIdx.y;
    #pragma unroll
    for (int i = 0; i < 4; i++)
        tile[ty + i * 8][tx] = W[(size_t)(kb + ty + i * 8) * DIM + nb + tx];
    __syncthreads();
    #pragma unroll
    for (int i = 0; i < 4; i++) {
        float x = tile[tx][ty + i * 8];
        __nv_bfloat16 h = __float2bfloat16(x);
        __nv_bfloat16 l = __float2bfloat16(x - __bfloat162float(h));
        Hi[(size_t)(nb + ty + i * 8) * DIM + kb + tx] = h;
        Lo[(size_t)(nb + ty + i * 8) * DIM + kb + tx] = l;
    }
}

// ------------- mma.sync GEMM core (validated R11) + fused epilogues --------
#define GS_LDS   40
#define GS_ROWB  (GS_LDS*2)
#define GS_ARR   (128*GS_ROWB)
#define GS_AHI   0
#define GS_ALO   GS_ARR
#define GS_BHI   (2*GS_ARR)
#define GS_BLO   (3*GS_ARR)
#define GS_STAGE (4*GS_ARR)
#define GEMM_SMEM (2*GS_STAGE)

__device__ __forceinline__ void gemm_load_stage(
    uint32_t smu, int s, int c,
    const __nv_bfloat16* Ahi, const __nv_bfloat16* Alo,
    const __nv_bfloat16* Bhi, const __nv_bfloat16* Blo,
    int mBase, int nBase, int t)
{
    const uint32_t st = smu + s * GS_STAGE;
    #pragma unroll
    for (int it = 0; it < 2; it++) {
        int u = t + it * 256;
        int r = u >> 2, sec = u & 3;
        uint32_t so = (uint32_t)(r * GS_ROWB + sec * 16);
        size_t ga = ((size_t)(mBase + r) * DIM + c * 32 + sec * 8);
        size_t gb = ((size_t)(nBase + r) * DIM + c * 32 + sec * 8);
        cp_async16(st + GS_AHI + so, Ahi + ga);
        cp_async16(st + GS_ALO + so, Alo + ga);
        cp_async16(st + GS_BHI + so, Bhi + gb);
        cp_async16(st + GS_BLO + so, Blo + gb);
    }
}

// Epilogue modes: Cf32 != nullptr -> fp32 C (bias added). Otherwise writes
// scaled bf16 hi/lo splits to Chi/Clo.
__device__ void gemm_mma_tile(const __nv_bfloat16* __restrict__ Ahi,
                              const __nv_bfloat16* __restrict__ Alo,
                              const __nv_bfloat16* __restrict__ Bhi,
                              const __nv_bfloat16* __restrict__ Blo,
                              const float* __restrict__ bias,
                              float* __restrict__ Cf32,
                              __nv_bfloat16* __restrict__ Chi,
                              __nv_bfloat16* __restrict__ Clo,
                              float scale)
{
    extern __shared__ char smc[];
    const uint32_t smu = smem_u32(smc);
    const int t    = threadIdx.x;
    const int wid  = t >> 5, lane = t & 31;
    const int gid  = lane >> 2, tig = lane & 3;
    const int wm   = wid >> 2;
    const int wn   = wid & 3;
    const int mBase = blockIdx.y * 128;
    const int nBase = blockIdx.x * 128;

    float acc[4][4][4];
    #pragma unroll
    for (int i = 0; i < 4; i++)
        #pragma unroll
        for (int j = 0; j < 4; j++)
            #pragma unroll
            for (int q = 0; q < 4; q++) acc[i][j][q] = 0.0f;

    gemm_load_stage(smu, 0, 0, Ahi, Alo, Bhi, Blo, mBase, nBase, t);
    cp_commit();

    const int NC = DIM / 32;
    for (int c = 0; c < NC; c++) {
        const int s = c & 1;
        if (c + 1 < NC) {
            gemm_load_stage(smu, (c + 1) & 1, c + 1,
                            Ahi, Alo, Bhi, Blo, mBase, nBase, t);
            cp_commit();
            cp_wait<1>();
        } else {
            cp_wait<0>();
        }
        __syncthreads();

        const __nv_bfloat16* As  = (const __nv_bfloat16*)(smc + s*GS_STAGE + GS_AHI);
        const __nv_bfloat16* Asl = (const __nv_bfloat16*)(smc + s*GS_STAGE + GS_ALO);
        const __nv_bfloat16* Bs  = (const __nv_bfloat16*)(smc + s*GS_STAGE + GS_BHI);
        const __nv_bfloat16* Bsl = (const __nv_bfloat16*)(smc + s*GS_STAGE + GS_BLO);

        #pragma unroll
        for (int ks = 0; ks < 2; ks++) {
            const int kof = ks * 16;
            uint32_t ah[4][4], al[4][4], bh[4][2], bl[4][2];
            #pragma unroll
            for (int mi = 0; mi < 4; mi++) {
                const int r = wm * 64 + mi * 16 + gid;
                const int base = r * GS_LDS + kof + 2 * tig;
                ah[mi][0] = *(const uint32_t*)(As  + base);
                ah[mi][1] = *(const uint32_t*)(As  + base + 8 * GS_LDS);
                ah[mi][2] = *(const uint32_t*)(As  + base + 8);
                ah[mi][3] = *(const uint32_t*)(As  + base + 8 * GS_LDS + 8);
                al[mi][0] = *(const uint32_t*)(Asl + base);
                al[mi][1] = *(const uint32_t*)(Asl + base + 8 * GS_LDS);
                al[mi][2] = *(const uint32_t*)(Asl + base + 8);
                al[mi][3] = *(const uint32_t*)(Asl + base + 8 * GS_LDS + 8);
            }
            #pragma unroll
            for (int ni = 0; ni < 4; ni++) {
                const int n = wn * 32 + ni * 8 + gid;
                const int base = n * GS_LDS + kof + 2 * tig;
                bh[ni][0] = *(const uint32_t*)(Bs  + base);
                bh[ni][1] = *(const uint32_t*)(Bs  + base + 8);
                bl[ni][0] = *(const uint32_t*)(Bsl + base);
                bl[ni][1] = *(const uint32_t*)(Bsl + base + 8);
            }
            #pragma unroll
            for (int mi = 0; mi < 4; mi++)
                #pragma unroll
                for (int ni = 0; ni < 4; ni++)
                    mma16816(acc[mi][ni], ah[mi], bh[ni]);
            #pragma unroll
            for (int mi = 0; mi < 4; mi++)
                #pragma unroll
                for (int ni = 0; ni < 4; ni++)
                    mma16816(acc[mi][ni], ah[mi], bl[ni]);
            #pragma unroll
            for (int mi = 0; mi < 4; mi++)
                #pragma unroll
                for (int ni = 0; ni < 4; ni++)
                    mma16816(acc[mi][ni], al[mi], bh[ni]);
        }
        __syncthreads();
    }

    #pragma unroll
    for (int mi = 0; mi < 4; mi++) {
        const int row = mBase + wm * 64 + mi * 16 + gid;
        #pragma unroll
        for (int ni = 0; ni < 4; ni++) {
            const int col = nBase + wn * 32 + ni * 8 + 2 * tig;
            const float b0 = bias[col], b1 = bias[col + 1];
            float v0 = acc[mi][ni][0] + b0, v1 = acc[mi][ni][1] + b1;
            float v2 = acc[mi][ni][2] + b0, v3 = acc[mi][ni][3] + b1;
            if (Cf32) {
                *(float2*)(Cf32 + (size_t)row * DIM + col) = make_float2(v0, v1);
                *(float2*)(Cf32 + (size_t)(row + 8) * DIM + col) = make_float2(v2, v3);
            } else {
                v0 *= scale; v1 *= scale; v2 *= scale; v3 *= scale;
                __nv_bfloat16 h0 = __float2bfloat16(v0);
                __nv_bfloat16 h1 = __float2bfloat16(v1);
                __nv_bfloat16 h2 = __float2bfloat16(v2);
                __nv_bfloat16 h3 = __float2bfloat16(v3);
                __nv_bfloat16 l0 = __float2bfloat16(v0 - __bfloat162float(h0));
                __nv_bfloat16 l1 = __float2bfloat16(v1 - __bfloat162float(h1));
                __nv_bfloat16 l2 = __float2bfloat16(v2 - __bfloat162float(h2));
                __nv_bfloat16 l3 = __float2bfloat16(v3 - __bfloat162float(h3));
                *(__nv_bfloat162*)(Chi + (size_t)row * DIM + col) =
                    __nv_bfloat162(h0, h1);
                *(__nv_bfloat162*)(Chi + (size_t)(row + 8) * DIM + col) =
                    __nv_bfloat162(h2, h3);
                *(__nv_bfloat162*)(Clo + (size_t)row * DIM + col) =
                    __nv_bfloat162(l0, l1);
                *(__nv_bfloat162*)(Clo + (size_t)(row + 8) * DIM + col) =
                    __nv_bfloat162(l2, l3);
            }
        }
    }
}

__global__ void __launch_bounds__(256, 1)
gemm_proj(const float* __restrict__ bq, const float* __restrict__ bk,
          const float* __restrict__ bv)
{
    const int z = blockIdx.z;
    const __nv_bfloat16* Ahi = g_in_hi + (size_t)z * MTOT * DIM;
    const __nv_bfloat16* Alo = g_in_lo + (size_t)z * MTOT * DIM;
    const __nv_bfloat16* Bhi = g_wt_hi + (size_t)z * DIM * DIM;
    const __nv_bfloat16* Blo = g_wt_lo + (size_t)z * DIM * DIM;
    if (z == 0)       // Q: scaled bf16 split, no fp32 round-trip
        gemm_mma_tile(Ahi, Alo, Bhi, Blo, bq, nullptr, g_q_hi, g_q_lo,
                      0.125f * 1.4426950408889634f);
    else if (z == 1)  // K: bf16 split
        gemm_mma_tile(Ahi, Alo, Bhi, Blo, bk, nullptr, g_k_hi, g_k_lo, 1.0f);
    else              // V: fp32 (transposed+split by vt_split)
        gemm_mma_tile(Ahi, Alo, Bhi, Blo, bv, g_V, nullptr, nullptr, 1.0f);
}

__global__ void __launch_bounds__(256, 1)
gemm_out(const float* __restrict__ bo, float* __restrict__ out)
{
    gemm_mma_tile(g_a_hi, g_a_lo,
                  g_wt_hi + 3ull * DIM * DIM, g_wt_lo + 3ull * DIM * DIM,
                  bo, out, nullptr, nullptr, 1.0f);
}

// ==================== attention on mma.sync (flash) =========================
#define A_LD   72
#define AQ_HI  0
#define AQ_LO  18432
#define AST0   36864
#define AK_HI  0
#define AK_LO  9216
#define AV_HI  18432
#define AV_LO  27648
#define AMSK   36864
#define AST_SZ 53248
#define ATTN_SMEM (AST0 + 2*AST_SZ)   // 143360

__device__ __forceinline__ void attn_load_stage(uint32_t sb, int s, int kt,
                                                int bb, int hh, int bh,
                                                int qt, int t)
{
    const uint32_t st = sb + AST0 + s * AST_SZ;
    #pragma unroll
    for (int it = 0; it < 4; ++it) {
        int u = t + it * 256;
        int sp = u >> 9, r = (u >> 3) & 63, sec = u & 7;
        const __nv_bfloat16* ks = (sp ? g_k_lo : g_k_hi)
            + ((size_t)(bb * SEQ + kt * 64 + r) * DIM + hh * HDIM + sec * 8);
        cp_async16(st + (sp ? AK_LO : AK_HI) + r * 144 + sec * 16, ks);
        const __half* vs = (sp ? g_vt_lo : g_vt_hi)
            + ((size_t)(bh * HDIM + r) * SEQ + kt * 64 + sec * 8);
        cp_async16(st + (sp ? AV_LO : AV_HI) + r * 144 + sec * 16, vs);
    }
    const __nv_bfloat16* ms = g_mfrag + ((size_t)(qt * 32 + kt) * 8192) + t * 32;
    #pragma unroll
    for (int c = 0; c < 4; ++c)
        cp_async16(st + AMSK + t * 64 + c * 16, ms + c * 8);
}

__global__ void __launch_bounds__(256)
attn_mma()
{
    extern __shared__ char sm[];
    const uint32_t sb = smem_u32(sm);
    const int t = threadIdx.x, w = t >> 5, lane = t & 31;
    const int gid = lane >> 2, tig = lane & 3;
    const int qt = blockIdx.x, hh = blockIdx.y, bb = blockIdx.z;
    const int q0 = qt * 128;
    const int bh = bb * NHEAD + hh;

    #pragma unroll
    for (int it = 0; it < 8; ++it) {
        int u = t + it * 256;
        int sp = u >> 10, r = (u >> 3) & 127, sec = u & 7;
        const __nv_bfloat16* src = (sp ? g_q_lo : g_q_hi)
            + ((size_t)(bb * SEQ + q0 + r) * DIM + hh * HDIM + sec * 8);
        cp_async16(sb + (sp ? AQ_LO : AQ_HI) + r * 144 + sec * 16, src);
    }
    attn_load_stage(sb, 0, 0, bb, hh, bh, qt, t);
    cp_commit();

    float oacc[8][4];
    #pragma unroll
    for (int i = 0; i < 8; i++)
        #pragma unroll
        for (int j = 0; j < 4; j++) oacc[i][j] = 0.0f;
    float lacc[4] = {0.0f, 0.0f, 0.0f, 0.0f};
    float m0 = -1e30f, m1 = -1e30f;

    const __nv_bfloat16* Qh = (const __nv_bfloat16*)(sm + AQ_HI);
    const __nv_bfloat16* Ql = (const __nv_bfloat16*)(sm + AQ_LO);
    const int arow = (w * 16 + gid) * A_LD;

    for (int kt = 0; kt < SEQ / 64; ++kt) {
        if (kt + 1 < SEQ / 64) {
            attn_load_stage(sb, (kt + 1) & 1, kt + 1, bb, hh, bh, qt, t);
            cp_commit();
            cp_wait<1>();
        } else {
            cp_wait<0>();
        }
        __syncthreads();

        const char* stp = sm + AST0 + (kt & 1) * AST_SZ;
        const __nv_bfloat16* Kh = (const __nv_bfloat16*)(stp + AK_HI);
        const __nv_bfloat16* Kl = (const __nv_bfloat16*)(stp + AK_LO);
        const __half* Vh = (const __half*)(stp + AV_HI);
        const __half* Vl = (const __half*)(stp + AV_LO);
        const uint32_t* Mw = (const uint32_t*)(stp + AMSK) + t * 16;

        // ---- S = Q K^T (bf16 3-split) ----
        float sacc[8][4];
        #pragma unroll
        for (int i = 0; i < 8; i++)
            #pragma unroll
            for (int j = 0; j < 4; j++) sacc[i][j] = 0.0f;

        #pragma unroll
        for (int kp = 0; kp < 4; ++kp) {
            const int ab = arow + kp * 16 + 2 * tig;
            uint32_t ah[4] = {
                *(const uint32_t*)(Qh + ab),
                *(const uint32_t*)(Qh + ab + 8 * A_LD),
                *(const uint32_t*)(Qh + ab + 8),
                *(const uint32_t*)(Qh + ab + 8 * A_LD + 8) };
            uint32_t al[4] = {
                *(const uint32_t*)(Ql + ab),
                *(const uint32_t*)(Ql + ab + 8 * A_LD),
                *(const uint32_t*)(Ql + ab + 8),
                *(const uint32_t*)(Ql + ab + 8 * A_LD + 8) };
            #pragma unroll
            for (int ni = 0; ni < 8; ++ni) {
                const int bbse = (ni * 8 + gid) * A_LD + kp * 16 + 2 * tig;
                uint32_t bhf[2] = { *(const uint32_t*)(Kh + bbse),
                                    *(const uint32_t*)(Kh + bbse + 8) };
                uint32_t blf[2] = { *(const uint32_t*)(Kl + bbse),
                                    *(const uint32_t*)(Kl + bbse + 8) };
                mma16816(sacc[ni], ah, bhf);
                mma16816(sacc[ni], ah, blf);
                mma16816(sacc[ni], al, bhf);
            }
        }

        // ---- online softmax (log2 units) ----
        float t0 = sacc[0][0], t1 = sacc[0][2];
        #pragma unroll
        for (int ni = 0; ni < 8; ++ni) {
            t0 = fmaxf(t0, fmaxf(sacc[ni][0], sacc[ni][1]));
            t1 = fmaxf(t1, fmaxf(sacc[ni][2], sacc[ni][3]));
        }
        t0 = fmaxf(t0, __shfl_xor_sync(0xffffffffu, t0, 1));
        t0 = fmaxf(t0, __shfl_xor_sync(0xffffffffu, t0, 2));
        t1 = fmaxf(t1, __shfl_xor_sync(0xffffffffu, t1, 1));
        t1 = fmaxf(t1, __shfl_xor_sync(0xffffffffu, t1, 2));
        const float nm0 = fmaxf(m0, t0), nm1 = fmaxf(m1, t1);
        const float f0 = ex2f(m0 - nm0), f1 = ex2f(m1 - nm1);
        m0 = nm0; m1 = nm1;
        #pragma unroll
        for (int ni = 0; ni < 8; ++ni) {
            oacc[ni][0] *= f0; oacc[ni][1] *= f0;
            oacc[ni][2] *= f1; oacc[ni][3] *= f1;
        }
        lacc[0] *= f0; lacc[1] *= f0; lacc[2] *= f1; lacc[3] *= f1;

        // ---- p = exp2(s - m) * mask, pack to fp16 (single-precision P) ----
        uint32_t PH[8][2];
        #pragma unroll
        for (int ni = 0; ni < 8; ++ni) {
            float p0 = ex2f(sacc[ni][0] - nm0);
            float p1 = ex2f(sacc[ni][1] - nm0);
            float p2 = ex2f(sacc[ni][2] - nm1);
            float p3 = ex2f(sacc[ni][3] - nm1);
            const uint32_t w0 = Mw[2 * ni], w1 = Mw[2 * ni + 1];
            p0 *= __uint_as_float(w0 << 16);
            p1 *= __uint_as_float(w0 & 0xFFFF0000u);
            p2 *= __uint_as_float(w1 << 16);
            p3 *= __uint_as_float(w1 & 0xFFFF0000u);
            PH[ni][0] = packh(p0, p1);
            PH[ni][1] = packh(p2, p3);
        }

        // ---- O += P V (fp16: 2 MMAs); l += P . ones (1 MMA) ----
        const uint32_t ones16[2] = {0x3C003C00u, 0x3C003C00u};
        #pragma unroll
        for (int kp = 0; kp < 4; ++kp) {
            uint32_t aph[4] = { PH[2*kp][0], PH[2*kp][1],
                                PH[2*kp+1][0], PH[2*kp+1][1] };
            mma16816h(lacc, aph, ones16);
            #pragma unroll
            for (int ni = 0; ni < 8; ++ni) {
                const int vb = (ni * 8 + gid) * A_LD + kp * 16 + 2 * tig;
                uint32_t bh2[2] = { *(const uint32_t*)(Vh + vb),
                                    *(const uint32_t*)(Vh + vb + 8) };
                uint32_t bl2[2] = { *(const uint32_t*)(Vl + vb),
                                    *(const uint32_t*)(Vl + vb + 8) };
                mma16816h(oacc[ni], aph, bh2);
                mma16816h(oacc[ni], aph, bl2);
            }
        }
        __syncthreads();
    }

    // ---- normalize + write bf16 hi/lo splits (feeds gemm_out directly) ----
    const float inv0 = 1.0f / lacc[0];
    const float inv1 = 1.0f / lacc[2];
    const size_t r0 = (size_t)(bb * SEQ + q0 + w * 16 + gid) * DIM + hh * HDIM;
    const size_t r1 = r0 + 8 * DIM;
    #pragma unroll
    for (int ni = 0; ni < 8; ++ni) {
        const int col = ni * 8 + 2 * tig;
        float o0 = oacc[ni][0] * inv0, o1 = oacc[ni][1] * inv0;
        float o2 = oacc[ni][2] * inv1, o3 = oacc[ni][3] * inv1;
        __nv_bfloat16 h0 = __float2bfloat16(o0);
        __nv_bfloat16 h1 = __float2bfloat16(o1);
        __nv_bfloat16 h2 = __float2bfloat16(o2);
        __nv_bfloat16 h3 = __float2bfloat16(o3);
        *(__nv_bfloat162*)(g_a_hi + r0 + col) = __nv_bfloat162(h0, h1);
        *(__nv_bfloat162*)(g_a_hi + r1 + col) = __nv_bfloat162(h2, h3);
        *(__nv_bfloat162*)(g_a_lo + r0 + col) = __nv_bfloat162(
            __float2bfloat16(o0 - __bfloat162float(h0)),
            __float2bfloat16(o1 - __bfloat162float(h1)));
        *(__nv_bfloat162*)(g_a_lo + r1 + col) = __nv_bfloat162(
            __float2bfloat16(o2 - __bfloat162float(h2)),
            __float2bfloat16(o3 - __bfloat162float(h3)));
    }
}

// =============================== launch ====================================
extern "C" void kernel_launch(void* const* d_in, const int* in_sizes, int n_in,
                              void* d_out, int out_size)
{
    const float* q    = (const float*)d_in[0];
    const float* k    = (const float*)d_in[1];
    const float* v    = (const float*)d_in[2];
    const int*   mask = (const int*)  d_in[3];
    const float* w_q  = (const float*)d_in[4];
    const float* b_q  = (const float*)d_in[5];
    const float* w_k  = (const float*)d_in[6];
    const float* b_k  = (const float*)d_in[7];
    const float* w_v  = (const float*)d_in[8];
    const float* b_v  = (const float*)d_in[9];
    const float* w_o  = (const float*)d_in[10];
    const float* b_o  = (const float*)d_in[11];
    float* out = (float*)d_out;

    (void)in_sizes; (void)n_in; (void)out_size;

    cudaFuncSetAttribute(gemm_proj,
                         cudaFuncAttributeMaxDynamicSharedMemorySize, GEMM_SMEM);
    cudaFuncSetAttribute(gemm_out,
                         cudaFuncAttributeMaxDynamicSharedMemorySize, GEMM_SMEM);
    cudaFuncSetAttribute(attn_mma,
                         cudaFuncAttributeMaxDynamicSharedMemorySize, ATTN_SMEM);

    // Pre-passes
    wT_split<<<dim3(32, 32, 4), dim3(32, 8)>>>(w_q, w_k, w_v, w_o);
    split_f32<<<4096, 256>>>(q, 0);
    split_f32<<<4096, 256>>>(k, 1);
    split_f32<<<4096, 256>>>(v, 2);
    mask_frag<<<(SEQ * SEQ / 2) / 256, 256>>>(mask);

    // QKV projections (Q/K epilogues write scaled bf16 splits directly)
    gemm_proj<<<dim3(8, 32, 3), 256, GEMM_SMEM>>>(b_q, b_k, b_v);

    // V transpose + fp16 split
    vt_split<<<dim3(SEQ / 32, HDIM / 32, BATCH * NHEAD), dim3(32, 8)>>>();

    // Attention (tensor cores; epilogue writes bf16 splits)
    attn_mma<<<dim3(SEQ / 128, NHEAD, BATCH), 256, ATTN_SMEM>>>();

    // Output projection
    gemm_out<<<dim3(8, 32), 256, GEMM_SMEM>>>(b_o, out);
}

// round 15
// speedup vs baseline: 3.0569x; 1.2854x over previous
#include <cuda_runtime.h>
#include <cuda_bf16.h>
#include <cuda_fp16.h>
#include <cstdint>

// ---------------------------------------------------------------------------
// MultiheadAttention: B=2, S=2048, D=1024, H=16, Dh=64
//   R15: attention QK^T -> fp16 2-MMA (Q 2-split, K single); PV -> fp16
//   1-MMA (V single); mask as packed bytes applied via PRMT/AND on packed
//   fp16 P. smem/CTA 90KB -> 2 CTAs/SM. Projections stay bf16 3-split
//   (out-proj error hits the output directly). GEMM core validated R11.
// ---------------------------------------------------------------------------

#define BATCH 2
#define SEQ   2048
#define DIM   1024
#define NHEAD 16
#define HDIM  64
#define MTOT  (BATCH*SEQ)   // 4096

// ----------------------------- device scratch ------------------------------
__device__ float g_V[MTOT*DIM];                     // fp32 V (for vt_split)
__device__ __nv_bfloat16 g_in_hi[3ull*MTOT*DIM];    // split q,k,v inputs
__device__ __nv_bfloat16 g_in_lo[3ull*MTOT*DIM];
__device__ __nv_bfloat16 g_a_hi[MTOT*DIM];          // attn output (split)
__device__ __nv_bfloat16 g_a_lo[MTOT*DIM];
__device__ __nv_bfloat16 g_wt_hi[4ull*DIM*DIM];     // W^T (K-major) splits
__device__ __nv_bfloat16 g_wt_lo[4ull*DIM*DIM];
__device__ __half g_q_hi[MTOT*DIM];                 // Q*0.125*log2e, fp16 2-split
__device__ __half g_q_lo[MTOT*DIM];
__device__ __half g_kh [MTOT*DIM];                  // K fp16 single
__device__ __half g_vt [(size_t)BATCH*NHEAD*HDIM*SEQ]; // V^T fp16 single
__device__ uint32_t g_mb[(size_t)SEQ*SEQ/4];        // mask bytes 0xFF/0x00

// ----------------------------- PTX helpers ---------------------------------
__device__ __forceinline__ uint32_t smem_u32(const void* p) {
    uint32_t a;
    asm("{ .reg .u64 t; cvta.to.shared.u64 t, %1; cvt.u32.u64 %0, t; }"
        : "=r"(a) : "l"(p));
    return a;
}
__device__ __forceinline__ void cp_async16(uint32_t saddr, const void* g) {
    asm volatile("cp.async.cg.shared.global [%0], [%1], 16;"
                 :: "r"(saddr), "l"(g) : "memory");
}
__device__ __forceinline__ void cp_commit() {
    asm volatile("cp.async.commit_group;" ::: "memory");
}
template <int N>
__device__ __forceinline__ void cp_wait() {
    asm volatile("cp.async.wait_group %0;" :: "n"(N) : "memory");
}
__device__ __forceinline__ void mma16816(float* c, const uint32_t* a,
                                         const uint32_t* b) {
    asm volatile(
        "mma.sync.aligned.m16n8k16.row.col.f32.bf16.bf16.f32 "
        "{%0,%1,%2,%3}, {%4,%5,%6,%7}, {%8,%9}, {%0,%1,%2,%3};"
        : "+f"(c[0]), "+f"(c[1]), "+f"(c[2]), "+f"(c[3])
        : "r"(a[0]), "r"(a[1]), "r"(a[2]), "r"(a[3]), "r"(b[0]), "r"(b[1]));
}
__device__ __forceinline__ void mma16816h(float* c, const uint32_t* a,
                                          const uint32_t* b) {
    asm volatile(
        "mma.sync.aligned.m16n8k16.row.col.f32.f16.f16.f32 "
        "{%0,%1,%2,%3}, {%4,%5,%6,%7}, {%8,%9}, {%0,%1,%2,%3};"
        : "+f"(c[0]), "+f"(c[1]), "+f"(c[2]), "+f"(c[3])
        : "r"(a[0]), "r"(a[1]), "r"(a[2]), "r"(a[3]), "r"(b[0]), "r"(b[1]));
}
__device__ __forceinline__ float ex2f(float x) {
    float y; asm("ex2.approx.f32 %0, %1;" : "=f"(y) : "f"(x)); return y;
}
// pack two f32 -> f16x2 (first arg lands in the low half)
__device__ __forceinline__ uint32_t packh(float lo, float hi) {
    uint32_t r;
    asm("cvt.rn.f16x2.f32 %0, %1, %2;" : "=r"(r) : "f"(hi), "f"(lo));
    return r;
}
__device__ __forceinline__ uint32_t prmt(uint32_t a, uint32_t sel) {
    uint32_t d;
    asm("prmt.b32 %0, %1, %2, %3;" : "=r"(d) : "r"(a), "r"(0u), "r"(sel));
    return d;
}

// ----------------------- split / transpose pre-passes ----------------------
// one launch, grid.y selects q/k/v
__global__ void __launch_bounds__(256)
split3(const float* __restrict__ q, const float* __restrict__ k,
       const float* __restrict__ v)
{
    const int which = blockIdx.y;
    const float* src = (which == 0) ? q : (which == 1) ? k : v;
    __nv_bfloat16* hi = g_in_hi + (size_t)which * MTOT * DIM;
    __nv_bfloat16* lo = g_in_lo + (size_t)which * MTOT * DIM;
    int i = blockIdx.x * 256 + threadIdx.x;
    float4 vv = ((const float4*)src)[i];
    float xs[4] = {vv.x, vv.y, vv.z, vv.w};
    union { __nv_bfloat16 b[4]; uint2 u; } H, L;
    #pragma unroll
    for (int j = 0; j < 4; j++) {
        __nv_bfloat16 h = __float2bfloat16(xs[j]);
        H.b[j] = h;
        L.b[j] = __float2bfloat16(xs[j] - __bfloat162float(h));
    }
    ((uint2*)hi)[i] = H.u;
    ((uint2*)lo)[i] = L.u;
}

// g_V [b*S+s][h*64+d] -> g_vt[(b*16+h)*64+d][s], fp16 single
__global__ void __launch_bounds__(256)
vt_split()
{
    __shared__ float tile[32][33];
    const int bh = blockIdx.z;
    const int s0 = blockIdx.x * 32, d0 = blockIdx.y * 32;
    const int b = bh >> 4, hh = bh & 15;
    const int tx = threadIdx.x, ty = threadIdx.y;
    #pragma unroll
    for (int i = 0; i < 4; i++)
        tile[ty + 8*i][tx] =
            g_V[(size_t)(b * SEQ + s0 + ty + 8*i) * DIM + hh * HDIM + d0 + tx];
    __syncthreads();
    #pragma unroll
    for (int i = 0; i < 4; i++) {
        size_t o = (size_t)(bh * HDIM + d0 + ty + 8*i) * SEQ + s0 + tx;
        g_vt[o] = __float2half(tile[tx][ty + 8*i]);
    }
}

// mask int32 -> packed bytes 0xFF/0x00, frag-ordered: word index
// W = (tile*256 + tid)*8 + ni; bytes = [p0,p1,p2,p3] for
// rows (gid, gid+8) x cols (col, col+1).
__global__ void __launch_bounds__(256)
mask_fragb(const int* __restrict__ mask)
{
    int W = blockIdx.x * 256 + threadIdx.x;        // 0 .. 1M-1
    int tile = W >> 11;
    int qt = tile >> 5, kt = tile & 31;
    int tid = (W >> 3) & 255, ni = W & 7;
    int w = tid >> 5, lane = tid & 31;
    int gid = lane >> 2, tig = lane & 3;
    int row = qt * 128 + w * 16 + gid;
    int col = kt * 64 + ni * 8 + tig * 2;
    uint32_t b0 = mask[(size_t)row * SEQ + col]          ? 0x000000FFu : 0u;
    uint32_t b1 = mask[(size_t)row * SEQ + col + 1]      ? 0x0000FF00u : 0u;
    uint32_t b2 = mask[(size_t)(row + 8) * SEQ + col]    ? 0x00FF0000u : 0u;
    uint32_t b3 = mask[(size_t)(row + 8) * SEQ + col + 1]? 0xFF000000u : 0u;
    g_mb[W] = b0 | b1 | b2 | b3;
}

// Transpose W[k][n] -> Wt[n][k], split to bf16 hi/lo. grid (32,32,4), blk (32,8)
__global__ void __launch_bounds__(256)
wT_split(const float* __restrict__ wq, const float* __restrict__ wk,
         const float* __restrict__ wv, const float* __restrict__ wo)
{
    __shared__ float tile[32][33];
    const int z = blockIdx.z;
    const float* W = (z == 0) ? wq : (z == 1) ? wk : (z == 2) ? wv : wo;
    __nv_bfloat16* Hi = g_wt_hi + (size_t)z * DIM * DIM;
    __nv_bfloat16* Lo = g_wt_lo + (size_t)z * DIM * DIM;
    const int kb = blockIdx.x * 32, nb = blockIdx.y * 32;
    const int tx = threadIdx.x, ty = threadIdx.y;
    #pragma unroll
    for (int i = 0; i < 4; i++)
        tile[ty + i * 8][tx] = W[(size_t)(kb + ty + i * 8) * DIM + nb + tx];
    __syncthreads();
    #pragma unroll
    for (int i = 0; i < 4; i++) {
        float x = tile[tx][ty + i * 8];
        __nv_bfloat16 h = __float2bfloat16(x);
        __nv_bfloat16 l = __float2bfloat16(x - __bfloat162float(h));
        Hi[(size_t)(nb + ty + i * 8) * DIM + kb + tx] = h;
        Lo[(size_t)(nb + ty + i * 8) * DIM + kb + tx] = l;
    }
}

// ------------- mma.sync GEMM core (validated R11) + fused epilogues --------
#define GS_LDS   40
#define GS_ROWB  (GS_LDS*2)
#define GS_ARR   (128*GS_ROWB)
#define GS_AHI   0
#define GS_ALO   GS_ARR
#define GS_BHI   (2*GS_ARR)
#define GS_BLO   (3*GS_ARR)
#define GS_STAGE (4*GS_ARR)
#define GEMM_SMEM (2*GS_STAGE)

__device__ __forceinline__ void gemm_load_stage(
    uint32_t smu, int s, int c,
    const __nv_bfloat16* Ahi, const __nv_bfloat16* Alo,
    const __nv_bfloat16* Bhi, const __nv_bfloat16* Blo,
    int mBase, int nBase, int t)
{
    const uint32_t st = smu + s * GS_STAGE;
    #pragma unroll
    for (int it = 0; it < 2; it++) {
        int u = t + it * 256;
        int r = u >> 2, sec = u & 3;
        uint32_t so = (uint32_t)(r * GS_ROWB + sec * 16);
        size_t ga = ((size_t)(mBase + r) * DIM + c * 32 + sec * 8);
        size_t gb = ((size_t)(nBase + r) * DIM + c * 32 + sec * 8);
        cp_async16(st + GS_AHI + so, Ahi + ga);
        cp_async16(st + GS_ALO + so, Alo + ga);
        cp_async16(st + GS_BHI + so, Bhi + gb);
        cp_async16(st + GS_BLO + so, Blo + gb);
    }
}

// Epilogue modes: Cf32 -> fp32 C. Else if Chlo -> scaled fp16 hi/lo splits.
// Else -> fp16 single (Chhi).
__device__ void gemm_mma_tile(const __nv_bfloat16* __restrict__ Ahi,
                              const __nv_bfloat16* __restrict__ Alo,
                              const __nv_bfloat16* __restrict__ Bhi,
                              const __nv_bfloat16* __restrict__ Blo,
                              const float* __restrict__ bias,
                              float* __restrict__ Cf32,
                              __half* __restrict__ Chhi,
                              __half* __restrict__ Chlo,
                              float scale)
{
    extern __shared__ char smc[];
    const uint32_t smu = smem_u32(smc);
    const int t    = threadIdx.x;
    const int wid  = t >> 5, lane = t & 31;
    const int gid  = lane >> 2, tig = lane & 3;
    const int wm   = wid >> 2;
    const int wn   = wid & 3;
    const int mBase = blockIdx.y * 128;
    const int nBase = blockIdx.x * 128;

    float acc[4][4][4];
    #pragma unroll
    for (int i = 0; i < 4; i++)
        #pragma unroll
        for (int j = 0; j < 4; j++)
            #pragma unroll
            for (int q = 0; q < 4; q++) acc[i][j][q] = 0.0f;

    gemm_load_stage(smu, 0, 0, Ahi, Alo, Bhi, Blo, mBase, nBase, t);
    cp_commit();

    const int NC = DIM / 32;
    for (int c = 0; c < NC; c++) {
        const int s = c & 1;
        if (c + 1 < NC) {
            gemm_load_stage(smu, (c + 1) & 1, c + 1,
                            Ahi, Alo, Bhi, Blo, mBase, nBase, t);
            cp_commit();
            cp_wait<1>();
        } else {
            cp_wait<0>();
        }
        __syncthreads();

        const __nv_bfloat16* As  = (const __nv_bfloat16*)(smc + s*GS_STAGE + GS_AHI);
        const __nv_bfloat16* Asl = (const __nv_bfloat16*)(smc + s*GS_STAGE + GS_ALO);
        const __nv_bfloat16* Bs  = (const __nv_bfloat16*)(smc + s*GS_STAGE + GS_BHI);
        const __nv_bfloat16* Bsl = (const __nv_bfloat16*)(smc + s*GS_STAGE + GS_BLO);

        #pragma unroll
        for (int ks = 0; ks < 2; ks++) {
            const int kof = ks * 16;
            uint32_t ah[4][4], al[4][4], bh[4][2], bl[4][2];
            #pragma unroll
            for (int mi = 0; mi < 4; mi++) {
                const int r = wm * 64 + mi * 16 + gid;
                const int base = r * GS_LDS + kof + 2 * tig;
                ah[mi][0] = *(const uint32_t*)(As  + base);
                ah[mi][1] = *(const uint32_t*)(As  + base + 8 * GS_LDS);
                ah[mi][2] = *(const uint32_t*)(As  + base + 8);
                ah[mi][3] = *(const uint32_t*)(As  + base + 8 * GS_LDS + 8);
                al[mi][0] = *(const uint32_t*)(Asl + base);
                al[mi][1] = *(const uint32_t*)(Asl + base + 8 * GS_LDS);
                al[mi][2] = *(const uint32_t*)(Asl + base + 8);
                al[mi][3] = *(const uint32_t*)(Asl + base + 8 * GS_LDS + 8);
            }
            #pragma unroll
            for (int ni = 0; ni < 4; ni++) {
                const int n = wn * 32 + ni * 8 + gid;
                const int base = n * GS_LDS + kof + 2 * tig;
                bh[ni][0] = *(const uint32_t*)(Bs  + base);
                bh[ni][1] = *(const uint32_t*)(Bs  + base + 8);
                bl[ni][0] = *(const uint32_t*)(Bsl + base);
                bl[ni][1] = *(const uint32_t*)(Bsl + base + 8);
            }
            #pragma unroll
            for (int mi = 0; mi < 4; mi++)
                #pragma unroll
                for (int ni = 0; ni < 4; ni++)
                    mma16816(acc[mi][ni], ah[mi], bh[ni]);
            #pragma unroll
            for (int mi = 0; mi < 4; mi++)
                #pragma unroll
                for (int ni = 0; ni < 4; ni++)
                    mma16816(acc[mi][ni], ah[mi], bl[ni]);
            #pragma unroll
            for (int mi = 0; mi < 4; mi++)
                #pragma unroll
                for (int ni = 0; ni < 4; ni++)
                    mma16816(acc[mi][ni], al[mi], bh[ni]);
        }
        __syncthreads();
    }

    #pragma unroll
    for (int mi = 0; mi < 4; mi++) {
        const int row = mBase + wm * 64 + mi * 16 + gid;
        #pragma unroll
        for (int ni = 0; ni < 4; ni++) {
            const int col = nBase + wn * 32 + ni * 8 + 2 * tig;
            const float b0 = bias[col], b1 = bias[col + 1];
            float v0 = acc[mi][ni][0] + b0, v1 = acc[mi][ni][1] + b1;
            float v2 = acc[mi][ni][2] + b0, v3 = acc[mi][ni][3] + b1;
            if (Cf32) {
                *(float2*)(Cf32 + (size_t)row * DIM + col) = make_float2(v0, v1);
                *(float2*)(Cf32 + (size_t)(row + 8) * DIM + col) = make_float2(v2, v3);
            } else if (Chlo) {
                v0 *= scale; v1 *= scale; v2 *= scale; v3 *= scale;
                __half h0 = __float2half(v0), h1 = __float2half(v1);
                __half h2 = __float2half(v2), h3 = __float2half(v3);
                *(uint32_t*)(Chhi + (size_t)row * DIM + col) =
                    packh(__half2float(h0), __half2float(h1));
                *(uint32_t*)(Chhi + (size_t)(row + 8) * DIM + col) =
                    packh(__half2float(h2), __half2float(h3));
                *(uint32_t*)(Chlo + (size_t)row * DIM + col) =
                    packh(v0 - __half2float(h0), v1 - __half2float(h1));
                *(uint32_t*)(Chlo + (size_t)(row + 8) * DIM + col) =
                    packh(v2 - __half2float(h2), v3 - __half2float(h3));
            } else {
                *(uint32_t*)(Chhi + (size_t)row * DIM + col) = packh(v0, v1);
                *(uint32_t*)(Chhi + (size_t)(row + 8) * DIM + col) = packh(v2, v3);
            }
        }
    }
}

__global__ void __launch_bounds__(256, 1)
gemm_proj(const float* __restrict__ bq, const float* __restrict__ bk,
          const float* __restrict__ bv)
{
    const int z = blockIdx.z;
    const __nv_bfloat16* Ahi = g_in_hi + (size_t)z * MTOT * DIM;
    const __nv_bfloat16* Alo = g_in_lo + (size_t)z * MTOT * DIM;
    const __nv_bfloat16* Bhi = g_wt_hi + (size_t)z * DIM * DIM;
    const __nv_bfloat16* Blo = g_wt_lo + (size_t)z * DIM * DIM;
    if (z == 0)       // Q: scaled fp16 2-split
        gemm_mma_tile(Ahi, Alo, Bhi, Blo, bq, nullptr, g_q_hi, g_q_lo,
                      0.125f * 1.4426950408889634f);
    else if (z == 1)  // K: fp16 single
        gemm_mma_tile(Ahi, Alo, Bhi, Blo, bk, nullptr, g_kh, nullptr, 1.0f);
    else              // V: fp32 (transposed+converted by vt_split)
        gemm_mma_tile(Ahi, Alo, Bhi, Blo, bv, g_V, nullptr, nullptr, 1.0f);
}

// attn output stays bf16 hi/lo -> gemm_out consumes bf16 (3-split, accurate)
__device__ __nv_bfloat16* const g_ahp = g_a_hi;
__global__ void __launch_bounds__(256, 1)
gemm_out(const float* __restrict__ bo, float* __restrict__ out)
{
    gemm_mma_tile(g_a_hi, g_a_lo,
                  g_wt_hi + 3ull * DIM * DIM, g_wt_lo + 3ull * DIM * DIM,
                  bo, out, nullptr, nullptr, 1.0f);
}

// ==================== attention on mma.sync (flash) =========================
// smem: Q hi/lo fp16 (128x72h rows), stages: K fp16 + V^T fp16 + mask bytes.
#define A_LD   72
#define AQ_HI  0
#define AQ_LO  18432
#define AST0   36864
#define AK     0
#define AV     9216
#define AMSK   18432
#define AST_SZ 26624
#define ATTN_SMEM (AST0 + 2*AST_SZ)   // 90112 -> 2 CTAs/SM

__device__ __forceinline__ void attn_load_stage(uint32_t sb, int s, int kt,
                                                int bb, int hh, int bh,
                                                int qt, int t)
{
    const uint32_t st = sb + AST0 + s * AST_SZ;
    #pragma unroll
    for (int it = 0; it < 2; ++it) {
        int u = t + it * 256;
        int r = u >> 3, sec = u & 7;
        const __half* ks = g_kh
            + ((size_t)(bb * SEQ + kt * 64 + r) * DIM + hh * HDIM + sec * 8);
        cp_async16(st + AK + r * 144 + sec * 16, ks);
        const __half* vs = g_vt
            + ((size_t)(bh * HDIM + r) * SEQ + kt * 64 + sec * 8);
        cp_async16(st + AV + r * 144 + sec * 16, vs);
    }
    const char* ms = (const char*)g_mb + ((size_t)(qt * 32 + kt) * 256 + t) * 32;
    cp_async16(st + AMSK + t * 32, ms);
    cp_async16(st + AMSK + t * 32 + 16, ms + 16);
}

__global__ void __launch_bounds__(256, 2)
attn_mma()
{
    extern __shared__ char sm[];
    const uint32_t sb = smem_u32(sm);
    const int t = threadIdx.x, w = t >> 5, lane = t & 31;
    const int gid = lane >> 2, tig = lane & 3;
    const int qt = blockIdx.x, hh = blockIdx.y, bb = blockIdx.z;
    const int q0 = qt * 128;
    const int bh = bb * NHEAD + hh;

    // Q hi/lo fp16, resident
    #pragma unroll
    for (int it = 0; it < 8; ++it) {
        int u = t + it * 256;
        int sp = u >> 10, r = (u >> 3) & 127, sec = u & 7;
        const __half* src = (sp ? g_q_lo : g_q_hi)
            + ((size_t)(bb * SEQ + q0 + r) * DIM + hh * HDIM + sec * 8);
        cp_async16(sb + (sp ? AQ_LO : AQ_HI) + r * 144 + sec * 16, src);
    }
    attn_load_stage(sb, 0, 0, bb, hh, bh, qt, t);
    cp_commit();

    float oacc[8][4];
    #pragma unroll
    for (int i = 0; i < 8; i++)
        #pragma unroll
        for (int j = 0; j < 4; j++) oacc[i][j] = 0.0f;
    float lacc[4] = {0.0f, 0.0f, 0.0f, 0.0f};
    float m0 = -1e30f, m1 = -1e30f;

    const __half* Qh = (const __half*)(sm + AQ_HI);
    const __half* Ql = (const __half*)(sm + AQ_LO);
    const int arow = (w * 16 + gid) * A_LD;

    for (int kt = 0; kt < SEQ / 64; ++kt) {
        if (kt + 1 < SEQ / 64) {
            attn_load_stage(sb, (kt + 1) & 1, kt + 1, bb, hh, bh, qt, t);
            cp_commit();
            cp_wait<1>();
        } else {
            cp_wait<0>();
        }
        __syncthreads();

        const char* stp = sm + AST0 + (kt & 1) * AST_SZ;
        const __half* Kh = (const __half*)(stp + AK);
        const __half* Vh = (const __half*)(stp + AV);
        const uint32_t* Mw = (const uint32_t*)(stp + AMSK) + t * 8;

        // ---- S = Q K^T (fp16: Q 2-split x K single = 2 MMAs) ----
        float sacc[8][4];
        #pragma unroll
        for (int i = 0; i < 8; i++)
            #pragma unroll
            for (int j = 0; j < 4; j++) sacc[i][j] = 0.0f;

        #pragma unroll
        for (int kp = 0; kp < 4; ++kp) {
            const int ab = arow + kp * 16 + 2 * tig;
            uint32_t ah[4] = {
                *(const uint32_t*)(Qh + ab),
                *(const uint32_t*)(Qh + ab + 8 * A_LD),
                *(const uint32_t*)(Qh + ab + 8),
                *(const uint32_t*)(Qh + ab + 8 * A_LD + 8) };
            uint32_t al[4] = {
                *(const uint32_t*)(Ql + ab),
                *(const uint32_t*)(Ql + ab + 8 * A_LD),
                *(const uint32_t*)(Ql + ab + 8),
                *(const uint32_t*)(Ql + ab + 8 * A_LD + 8) };
            #pragma unroll
            for (int ni = 0; ni < 8; ++ni) {
                const int bbse = (ni * 8 + gid) * A_LD + kp * 16 + 2 * tig;
                uint32_t bhf[2] = { *(const uint32_t*)(Kh + bbse),
                                    *(const uint32_t*)(Kh + bbse + 8) };
                mma16816h(sacc[ni], ah, bhf);
                mma16816h(sacc[ni], al, bhf);
            }
        }

        // ---- online softmax (log2 units) ----
        float t0 = sacc[0][0], t1 = sacc[0][2];
        #pragma unroll
        for (int ni = 0; ni < 8; ++ni) {
            t0 = fmaxf(t0, fmaxf(sacc[ni][0], sacc[ni][1]));
            t1 = fmaxf(t1, fmaxf(sacc[ni][2], sacc[ni][3]));
        }
        t0 = fmaxf(t0, __shfl_xor_sync(0xffffffffu, t0, 1));
        t0 = fmaxf(t0, __shfl_xor_sync(0xffffffffu, t0, 2));
        t1 = fmaxf(t1, __shfl_xor_sync(0xffffffffu, t1, 1));
        t1 = fmaxf(t1, __shfl_xor_sync(0xffffffffu, t1, 2));
        const float nm0 = fmaxf(m0, t0), nm1 = fmaxf(m1, t1);
        const float f0 = ex2f(m0 - nm0), f1 = ex2f(m1 - nm1);
        m0 = nm0; m1 = nm1;
        #pragma unroll
        for (int ni = 0; ni < 8; ++ni) {
            oacc[ni][0] *= f0; oacc[ni][1] *= f0;
            oacc[ni][2] *= f1; oacc[ni][3] *= f1;
        }
        lacc[0] *= f0; lacc[1] *= f0; lacc[2] *= f1; lacc[3] *= f1;

        // ---- p = exp2(s - m), pack fp16, mask via PRMT/AND ----
        uint32_t PH[8][2];
        #pragma unroll
        for (int ni = 0; ni < 8; ++ni) {
            float p0 = ex2f(sacc[ni][0] - nm0);
            float p1 = ex2f(sacc[ni][1] - nm0);
            float p2 = ex2f(sacc[ni][2] - nm1);
            float p3 = ex2f(sacc[ni][3] - nm1);
            const uint32_t mw = Mw[ni];
            PH[ni][0] = packh(p0, p1) & prmt(mw, 0x1100u);
            PH[ni][1] = packh(p2, p3) & prmt(mw, 0x3322u);
        }

        // ---- O += P V (1 MMA); l += P . ones (1 MMA) ----
        const uint32_t ones16[2] = {0x3C003C00u, 0x3C003C00u};
        #pragma unroll
        for (int kp = 0; kp < 4; ++kp) {
            uint32_t aph[4] = { PH[2*kp][0], PH[2*kp][1],
                                PH[2*kp+1][0], PH[2*kp+1][1] };
            mma16816h(lacc, aph, ones16);
            #pragma unroll
            for (int ni = 0; ni < 8; ++ni) {
                const int vb = (ni * 8 + gid) * A_LD + kp * 16 + 2 * tig;
                uint32_t bh2[2] = { *(const uint32_t*)(Vh + vb),
                                    *(const uint32_t*)(Vh + vb + 8) };
                mma16816h(oacc[ni], aph, bh2);
            }
        }
        __syncthreads();
    }

    // ---- normalize + write bf16 hi/lo splits (feeds gemm_out) ----
    const float inv0 = 1.0f / lacc[0];
    const float inv1 = 1.0f / lacc[2];
    const size_t r0 = (size_t)(bb * SEQ + q0 + w * 16 + gid) * DIM + hh * HDIM;
    const size_t r1 = r0 + 8 * DIM;
    #pragma unroll
    for (int ni = 0; ni < 8; ++ni) {
        const int col = ni * 8 + 2 * tig;
        float o0 = oacc[ni][0] * inv0, o1 = oacc[ni][1] * inv0;
        float o2 = oacc[ni][2] * inv1, o3 = oacc[ni][3] * inv1;
        __nv_bfloat16 h0 = __float2bfloat16(o0);
        __nv_bfloat16 h1 = __float2bfloat16(o1);
        __nv_bfloat16 h2 = __float2bfloat16(o2);
        __nv_bfloat16 h3 = __float2bfloat16(o3);
        *(__nv_bfloat162*)(g_a_hi + r0 + col) = __nv_bfloat162(h0, h1);
        *(__nv_bfloat162*)(g_a_hi + r1 + col) = __nv_bfloat162(h2, h3);
        *(__nv_bfloat162*)(g_a_lo + r0 + col) = __nv_bfloat162(
            __float2bfloat16(o0 - __bfloat162float(h0)),
            __float2bfloat16(o1 - __bfloat162float(h1)));
        *(__nv_bfloat162*)(g_a_lo + r1 + col) = __nv_bfloat162(
            __float2bfloat16(o2 - __bfloat162float(h2)),
            __float2bfloat16(o3 - __bfloat162float(h3)));
    }
}

// =============================== launch ====================================
extern "C" void kernel_launch(void* const* d_in, const int* in_sizes, int n_in,
                              void* d_out, int out_size)
{
    const float* q    = (const float*)d_in[0];
    const float* k    = (const float*)d_in[1];
    const float* v    = (const float*)d_in[2];
    const int*   mask = (const int*)  d_in[3];
    const float* w_q  = (const float*)d_in[4];
    const float* b_q  = (const float*)d_in[5];
    const float* w_k  = (const float*)d_in[6];
    const float* b_k  = (const float*)d_in[7];
    const float* w_v  = (const float*)d_in[8];
    const float* b_v  = (const float*)d_in[9];
    const float* w_o  = (const float*)d_in[10];
    const float* b_o  = (const float*)d_in[11];
    float* out = (float*)d_out;

    (void)in_sizes; (void)n_in; (void)out_size;

    cudaFuncSetAttribute(gemm_proj,
                         cudaFuncAttributeMaxDynamicSharedMemorySize, GEMM_SMEM);
    cudaFuncSetAttribute(gemm_out,
                         cudaFuncAttributeMaxDynamicSharedMemorySize, GEMM_SMEM);
    cudaFuncSetAttribute(attn_mma,
                         cudaFuncAttributeMaxDynamicSharedMemorySize, ATTN_SMEM);

    // Pre-passes
    wT_split<<<dim3(32, 32, 4), dim3(32, 8)>>>(w_q, w_k, w_v, w_o);
    split3<<<dim3(4096, 3), 256>>>(q, k, v);
    mask_fragb<<<(SEQ * SEQ / 4) / 256, 256>>>(mask);

    // QKV projections (Q -> scaled fp16 2-split, K -> fp16, V -> fp32)
    gemm_proj<<<dim3(8, 32, 3), 256, GEMM_SMEM>>>(b_q, b_k, b_v);

    // V transpose -> fp16
    vt_split<<<dim3(SEQ / 32, HDIM / 32, BATCH * NHEAD), dim3(32, 8)>>>();

    // Attention (fp16 tensor cores, 2 CTAs/SM)
    attn_mma<<<dim3(SEQ / 128, NHEAD, BATCH), 256, ATTN_SMEM>>>();

    // Output projection (bf16 3-split, accurate)
    gemm_out<<<dim3(8, 32), 256, GEMM_SMEM>>>(b_o, out);
}

// round 16
// speedup vs baseline: 3.8918x; 1.2731x over previous
#include <cuda_runtime.h>
#include <cuda_bf16.h>
#include <cuda_fp16.h>
#include <cstdint>

// ---------------------------------------------------------------------------
// MultiheadAttention: B=2, S=2048, D=1024, H=16, Dh=64
//   R16: all four projection GEMMs -> fp16 2-MMA (A fp16 2-split x W fp16
//   single). Stage smem 40KB->30KB => 2 CTAs/SM (was tensor=44.8%, occ=12.5%).
//   attn output + out-proj input now fp16 hi/lo. Attention core unchanged
//   from R15 (fp16 QK 2-MMA, PV 1-MMA, PRMT mask).
// ---------------------------------------------------------------------------

#define BATCH 2
#define SEQ   2048
#define DIM   1024
#define NHEAD 16
#define HDIM  64
#define MTOT  (BATCH*SEQ)   // 4096

// ----------------------------- device scratch ------------------------------
__device__ float g_V[MTOT*DIM];                     // fp32 V (for vt_split)
__device__ __half g_in_hi[3ull*MTOT*DIM];           // fp16 2-split q,k,v
__device__ __half g_in_lo[3ull*MTOT*DIM];
__device__ __half g_a_hi[MTOT*DIM];                 // attn output fp16 2-split
__device__ __half g_a_lo[MTOT*DIM];
__device__ __half g_wt[4ull*DIM*DIM];               // W^T (K-major) fp16
__device__ __half g_q_hi[MTOT*DIM];                 // Q*0.125*log2e, 2-split
__device__ __half g_q_lo[MTOT*DIM];
__device__ __half g_kh [MTOT*DIM];                  // K fp16 single
__device__ __half g_vt [(size_t)BATCH*NHEAD*HDIM*SEQ]; // V^T fp16 single
__device__ uint32_t g_mb[(size_t)SEQ*SEQ/4];        // mask bytes 0xFF/0x00

// ----------------------------- PTX helpers ---------------------------------
__device__ __forceinline__ uint32_t smem_u32(const void* p) {
    uint32_t a;
    asm("{ .reg .u64 t; cvta.to.shared.u64 t, %1; cvt.u32.u64 %0, t; }"
        : "=r"(a) : "l"(p));
    return a;
}
__device__ __forceinline__ void cp_async16(uint32_t saddr, const void* g) {
    asm volatile("cp.async.cg.shared.global [%0], [%1], 16;"
                 :: "r"(saddr), "l"(g) : "memory");
}
__device__ __forceinline__ void cp_commit() {
    asm volatile("cp.async.commit_group;" ::: "memory");
}
template <int N>
__device__ __forceinline__ void cp_wait() {
    asm volatile("cp.async.wait_group %0;" :: "n"(N) : "memory");
}
__device__ __forceinline__ void mma16816h(float* c, const uint32_t* a,
                                          const uint32_t* b) {
    asm volatile(
        "mma.sync.aligned.m16n8k16.row.col.f32.f16.f16.f32 "
        "{%0,%1,%2,%3}, {%4,%5,%6,%7}, {%8,%9}, {%0,%1,%2,%3};"
        : "+f"(c[0]), "+f"(c[1]), "+f"(c[2]), "+f"(c[3])
        : "r"(a[0]), "r"(a[1]), "r"(a[2]), "r"(a[3]), "r"(b[0]), "r"(b[1]));
}
__device__ __forceinline__ float ex2f(float x) {
    float y; asm("ex2.approx.f32 %0, %1;" : "=f"(y) : "f"(x)); return y;
}
// pack two f32 -> f16x2 (first arg lands in the low half)
__device__ __forceinline__ uint32_t packh(float lo, float hi) {
    uint32_t r;
    asm("cvt.rn.f16x2.f32 %0, %1, %2;" : "=r"(r) : "f"(hi), "f"(lo));
    return r;
}
__device__ __forceinline__ uint32_t prmt(uint32_t a, uint32_t sel) {
    uint32_t d;
    asm("prmt.b32 %0, %1, %2, %3;" : "=r"(d) : "r"(a), "r"(0u), "r"(sel));
    return d;
}

// ----------------------- split / transpose pre-passes ----------------------
// inputs -> fp16 hi/lo; grid.y selects q/k/v
__global__ void __launch_bounds__(256)
split3(const float* __restrict__ q, const float* __restrict__ k,
       const float* __restrict__ v)
{
    const int which = blockIdx.y;
    const float* src = (which == 0) ? q : (which == 1) ? k : v;
    __half* hi = g_in_hi + (size_t)which * MTOT * DIM;
    __half* lo = g_in_lo + (size_t)which * MTOT * DIM;
    int i = blockIdx.x * 256 + threadIdx.x;
    float4 vv = ((const float4*)src)[i];
    float xs[4] = {vv.x, vv.y, vv.z, vv.w};
    uint2 H, L;
    float h0 = __half2float(__float2half(xs[0]));
    float h1 = __half2float(__float2half(xs[1]));
    float h2 = __half2float(__float2half(xs[2]));
    float h3 = __half2float(__float2half(xs[3]));
    H.x = packh(h0, h1); H.y = packh(h2, h3);
    L.x = packh(xs[0] - h0, xs[1] - h1);
    L.y = packh(xs[2] - h2, xs[3] - h3);
    ((uint2*)hi)[i] = H;
    ((uint2*)lo)[i] = L;
}

// g_V [b*S+s][h*64+d] -> g_vt[(b*16+h)*64+d][s], fp16 single
__global__ void __launch_bounds__(256)
vt_split()
{
    __shared__ float tile[32][33];
    const int bh = blockIdx.z;
    const int s0 = blockIdx.x * 32, d0 = blockIdx.y * 32;
    const int b = bh >> 4, hh = bh & 15;
    const int tx = threadIdx.x, ty = threadIdx.y;
    #pragma unroll
    for (int i = 0; i < 4; i++)
        tile[ty + 8*i][tx] =
            g_V[(size_t)(b * SEQ + s0 + ty + 8*i) * DIM + hh * HDIM + d0 + tx];
    __syncthreads();
    #pragma unroll
    for (int i = 0; i < 4; i++) {
        size_t o = (size_t)(bh * HDIM + d0 + ty + 8*i) * SEQ + s0 + tx;
        g_vt[o] = __float2half(tile[tx][ty + 8*i]);
    }
}

// mask int32 -> packed bytes 0xFF/0x00, frag-ordered (validated R15)
__global__ void __launch_bounds__(256)
mask_fragb(const int* __restrict__ mask)
{
    int W = blockIdx.x * 256 + threadIdx.x;        // 0 .. 1M-1
    int tile = W >> 11;
    int qt = tile >> 5, kt = tile & 31;
    int tid = (W >> 3) & 255, ni = W & 7;
    int w = tid >> 5, lane = tid & 31;
    int gid = lane >> 2, tig = lane & 3;
    int row = qt * 128 + w * 16 + gid;
    int col = kt * 64 + ni * 8 + tig * 2;
    uint32_t b0 = mask[(size_t)row * SEQ + col]          ? 0x000000FFu : 0u;
    uint32_t b1 = mask[(size_t)row * SEQ + col + 1]      ? 0x0000FF00u : 0u;
    uint32_t b2 = mask[(size_t)(row + 8) * SEQ + col]    ? 0x00FF0000u : 0u;
    uint32_t b3 = mask[(size_t)(row + 8) * SEQ + col + 1]? 0xFF000000u : 0u;
    g_mb[W] = b0 | b1 | b2 | b3;
}

// Transpose W[k][n] -> Wt[n][k], fp16 single. grid (32,32,4), blk (32,8)
__global__ void __launch_bounds__(256)
wT_split(const float* __restrict__ wq, const float* __restrict__ wk,
         const float* __restrict__ wv, const float* __restrict__ wo)
{
    __shared__ float tile[32][33];
    const int z = blockIdx.z;
    const float* W = (z == 0) ? wq : (z == 1) ? wk : (z == 2) ? wv : wo;
    __half* Wt = g_wt + (size_t)z * DIM * DIM;
    const int kb = blockIdx.x * 32, nb = blockIdx.y * 32;
    const int tx = threadIdx.x, ty = threadIdx.y;
    #pragma unroll
    for (int i = 0; i < 4; i++)
        tile[ty + i * 8][tx] = W[(size_t)(kb + ty + i * 8) * DIM + nb + tx];
    __syncthreads();
    #pragma unroll
    for (int i = 0; i < 4; i++)
        Wt[(size_t)(nb + ty + i * 8) * DIM + kb + tx] =
            __float2half(tile[tx][ty + i * 8]);
}

// ---------------- fp16 2-MMA GEMM: C = (Ahi+Alo) @ Wt^T + bias -------------
// Block 128x128, BK=32; 8 warps (2m x 4n), warp tile 64x32. Stage: Ahi, Alo,
// B fp16 (row stride 40 halfs = conflict-free). 2 stages = 60KB -> 2 CTAs/SM.
#define GS_LDS   40
#define GS_ROWB  (GS_LDS*2)
#define GS_ARR   (128*GS_ROWB)          // 10240
#define GS_AHI   0
#define GS_ALO   GS_ARR
#define GS_B     (2*GS_ARR)
#define GS_STAGE (3*GS_ARR)             // 30720
#define GEMM_SMEM (2*GS_STAGE)          // 61440

__device__ __forceinline__ void gemm_load_stage(
    uint32_t smu, int s, int c,
    const __half* Ahi, const __half* Alo, const __half* B,
    int mBase, int nBase, int t)
{
    const uint32_t st = smu + s * GS_STAGE;
    #pragma unroll
    for (int it = 0; it < 2; it++) {
        int u = t + it * 256;
        int r = u >> 2, sec = u & 3;
        uint32_t so = (uint32_t)(r * GS_ROWB + sec * 16);
        size_t ga = ((size_t)(mBase + r) * DIM + c * 32 + sec * 8);
        size_t gb = ((size_t)(nBase + r) * DIM + c * 32 + sec * 8);
        cp_async16(st + GS_AHI + so, Ahi + ga);
        cp_async16(st + GS_ALO + so, Alo + ga);
        cp_async16(st + GS_B   + so, B   + gb);
    }
}

// Epilogue modes: Cf32 -> fp32. Else if Chlo -> scaled fp16 hi/lo. Else fp16.
__device__ void gemm_mma_tile(const __half* __restrict__ Ahi,
                              const __half* __restrict__ Alo,
                              const __half* __restrict__ B,
                              const float* __restrict__ bias,
                              float* __restrict__ Cf32,
                              __half* __restrict__ Chhi,
                              __half* __restrict__ Chlo,
                              float scale)
{
    extern __shared__ char smc[];
    const uint32_t smu = smem_u32(smc);
    const int t    = threadIdx.x;
    const int wid  = t >> 5, lane = t & 31;
    const int gid  = lane >> 2, tig = lane & 3;
    const int wm   = wid >> 2;
    const int wn   = wid & 3;
    const int mBase = blockIdx.y * 128;
    const int nBase = blockIdx.x * 128;

    float acc[4][4][4];
    #pragma unroll
    for (int i = 0; i < 4; i++)
        #pragma unroll
        for (int j = 0; j < 4; j++)
            #pragma unroll
            for (int q = 0; q < 4; q++) acc[i][j][q] = 0.0f;

    gemm_load_stage(smu, 0, 0, Ahi, Alo, B, mBase, nBase, t);
    cp_commit();

    const int NC = DIM / 32;
    for (int c = 0; c < NC; c++) {
        const int s = c & 1;
        if (c + 1 < NC) {
            gemm_load_stage(smu, (c + 1) & 1, c + 1,
                            Ahi, Alo, B, mBase, nBase, t);
            cp_commit();
            cp_wait<1>();
        } else {
            cp_wait<0>();
        }
        __syncthreads();

        const __half* As  = (const __half*)(smc + s*GS_STAGE + GS_AHI);
        const __half* Asl = (const __half*)(smc + s*GS_STAGE + GS_ALO);
        const __half* Bs  = (const __half*)(smc + s*GS_STAGE + GS_B);

        #pragma unroll
        for (int ks = 0; ks < 2; ks++) {
            const int kof = ks * 16;
            uint32_t ah[4][4], al[4][4], bh[4][2];
            #pragma unroll
            for (int mi = 0; mi < 4; mi++) {
                const int r = wm * 64 + mi * 16 + gid;
                const int base = r * GS_LDS + kof + 2 * tig;
                ah[mi][0] = *(const uint32_t*)(As  + base);
                ah[mi][1] = *(const uint32_t*)(As  + base + 8 * GS_LDS);
                ah[mi][2] = *(const uint32_t*)(As  + base + 8);
                ah[mi][3] = *(const uint32_t*)(As  + base + 8 * GS_LDS + 8);
                al[mi][0] = *(const uint32_t*)(Asl + base);
                al[mi][1] = *(const uint32_t*)(Asl + base + 8 * GS_LDS);
                al[mi][2] = *(const uint32_t*)(Asl + base + 8);
                al[mi][3] = *(const uint32_t*)(Asl + base + 8 * GS_LDS + 8);
            }
            #pragma unroll
            for (int ni = 0; ni < 4; ni++) {
                const int n = wn * 32 + ni * 8 + gid;
                const int base = n * GS_LDS + kof + 2 * tig;
                bh[ni][0] = *(const uint32_t*)(Bs + base);
                bh[ni][1] = *(const uint32_t*)(Bs + base + 8);
            }
            #pragma unroll
            for (int mi = 0; mi < 4; mi++)
                #pragma unroll
                for (int ni = 0; ni < 4; ni++)
                    mma16816h(acc[mi][ni], ah[mi], bh[ni]);
            #pragma unroll
            for (int mi = 0; mi < 4; mi++)
                #pragma unroll
                for (int ni = 0; ni < 4; ni++)
                    mma16816h(acc[mi][ni], al[mi], bh[ni]);
        }
        __syncthreads();
    }

    #pragma unroll
    for (int mi = 0; mi < 4; mi++) {
        const int row = mBase + wm * 64 + mi * 16 + gid;
        #pragma unroll
        for (int ni = 0; ni < 4; ni++) {
            const int col = nBase + wn * 32 + ni * 8 + 2 * tig;
            const float b0 = bias[col], b1 = bias[col + 1];
            float v0 = acc[mi][ni][0] + b0, v1 = acc[mi][ni][1] + b1;
            float v2 = acc[mi][ni][2] + b0, v3 = acc[mi][ni][3] + b1;
            if (Cf32) {
                *(float2*)(Cf32 + (size_t)row * DIM + col) = make_float2(v0, v1);
                *(float2*)(Cf32 + (size_t)(row + 8) * DIM + col) = make_float2(v2, v3);
            } else if (Chlo) {
                v0 *= scale; v1 *= scale; v2 *= scale; v3 *= scale;
                float h0 = __half2float(__float2half(v0));
                float h1 = __half2float(__float2half(v1));
                float h2 = __half2float(__float2half(v2));
                float h3 = __half2float(__float2half(v3));
                *(uint32_t*)(Chhi + (size_t)row * DIM + col)       = packh(h0, h1);
                *(uint32_t*)(Chhi + (size_t)(row + 8) * DIM + col) = packh(h2, h3);
                *(uint32_t*)(Chlo + (size_t)row * DIM + col)       =
                    packh(v0 - h0, v1 - h1);
                *(uint32_t*)(Chlo + (size_t)(row + 8) * DIM + col) =
                    packh(v2 - h2, v3 - h3);
            } else {
                *(uint32_t*)(Chhi + (size_t)row * DIM + col)       = packh(v0, v1);
                *(uint32_t*)(Chhi + (size_t)(row + 8) * DIM + col) = packh(v2, v3);
            }
        }
    }
}

__global__ void __launch_bounds__(256, 2)
gemm_proj(const float* __restrict__ bq, const float* __restrict__ bk,
          const float* __restrict__ bv)
{
    const int z = blockIdx.z;
    const __half* Ahi = g_in_hi + (size_t)z * MTOT * DIM;
    const __half* Alo = g_in_lo + (size_t)z * MTOT * DIM;
    const __half* Bw  = g_wt + (size_t)z * DIM * DIM;
    if (z == 0)       // Q: scaled fp16 2-split
        gemm_mma_tile(Ahi, Alo, Bw, bq, nullptr, g_q_hi, g_q_lo,
                      0.125f * 1.4426950408889634f);
    else if (z == 1)  // K: fp16 single
        gemm_mma_tile(Ahi, Alo, Bw, bk, nullptr, g_kh, nullptr, 1.0f);
    else              // V: fp32 (transposed+converted by vt_split)
        gemm_mma_tile(Ahi, Alo, Bw, bv, g_V, nullptr, nullptr, 1.0f);
}

__global__ void __launch_bounds__(256, 2)
gemm_out(const float* __restrict__ bo, float* __restrict__ out)
{
    gemm_mma_tile(g_a_hi, g_a_lo, g_wt + 3ull * DIM * DIM,
                  bo, out, nullptr, nullptr, 1.0f);
}

// ==================== attention on mma.sync (flash, R15) ====================
#define A_LD   72
#define AQ_HI  0
#define AQ_LO  18432
#define AST0   36864
#define AK     0
#define AV     9216
#define AMSK   18432
#define AST_SZ 26624
#define ATTN_SMEM (AST0 + 2*AST_SZ)   // 90112 -> 2 CTAs/SM

__device__ __forceinline__ void attn_load_stage(uint32_t sb, int s, int kt,
                                                int bb, int hh, int bh,
                                                int qt, int t)
{
    const uint32_t st = sb + AST0 + s * AST_SZ;
    #pragma unroll
    for (int it = 0; it < 2; ++it) {
        int u = t + it * 256;
        int r = u >> 3, sec = u & 7;
        const __half* ks = g_kh
            + ((size_t)(bb * SEQ + kt * 64 + r) * DIM + hh * HDIM + sec * 8);
        cp_async16(st + AK + r * 144 + sec * 16, ks);
        const __half* vs = g_vt
            + ((size_t)(bh * HDIM + r) * SEQ + kt * 64 + sec * 8);
        cp_async16(st + AV + r * 144 + sec * 16, vs);
    }
    const char* ms = (const char*)g_mb + ((size_t)(qt * 32 + kt) * 256 + t) * 32;
    cp_async16(st + AMSK + t * 32, ms);
    cp_async16(st + AMSK + t * 32 + 16, ms + 16);
}

__global__ void __launch_bounds__(256, 2)
attn_mma()
{
    extern __shared__ char sm[];
    const uint32_t sb = smem_u32(sm);
    const int t = threadIdx.x, w = t >> 5, lane = t & 31;
    const int gid = lane >> 2, tig = lane & 3;
    const int qt = blockIdx.x, hh = blockIdx.y, bb = blockIdx.z;
    const int q0 = qt * 128;
    const int bh = bb * NHEAD + hh;

    #pragma unroll
    for (int it = 0; it < 8; ++it) {
        int u = t + it * 256;
        int sp = u >> 10, r = (u >> 3) & 127, sec = u & 7;
        const __half* src = (sp ? g_q_lo : g_q_hi)
            + ((size_t)(bb * SEQ + q0 + r) * DIM + hh * HDIM + sec * 8);
        cp_async16(sb + (sp ? AQ_LO : AQ_HI) + r * 144 + sec * 16, src);
    }
    attn_load_stage(sb, 0, 0, bb, hh, bh, qt, t);
    cp_commit();

    float oacc[8][4];
    #pragma unroll
    for (int i = 0; i < 8; i++)
        #pragma unroll
        for (int j = 0; j < 4; j++) oacc[i][j] = 0.0f;
    float lacc[4] = {0.0f, 0.0f, 0.0f, 0.0f};
    float m0 = -1e30f, m1 = -1e30f;

    const __half* Qh = (const __half*)(sm + AQ_HI);
    const __half* Ql = (const __half*)(sm + AQ_LO);
    const int arow = (w * 16 + gid) * A_LD;

    for (int kt = 0; kt < SEQ / 64; ++kt) {
        if (kt + 1 < SEQ / 64) {
            attn_load_stage(sb, (kt + 1) & 1, kt + 1, bb, hh, bh, qt, t);
            cp_commit();
            cp_wait<1>();
        } else {
            cp_wait<0>();
        }
        __syncthreads();

        const char* stp = sm + AST0 + (kt & 1) * AST_SZ;
        const __half* Kh = (const __half*)(stp + AK);
        const __half* Vh = (const __half*)(stp + AV);
        const uint32_t* Mw = (const uint32_t*)(stp + AMSK) + t * 8;

        // ---- S = Q K^T (fp16: Q 2-split x K single = 2 MMAs) ----
        float sacc[8][4];
        #pragma unroll
        for (int i = 0; i < 8; i++)
            #pragma unroll
            for (int j = 0; j < 4; j++) sacc[i][j] = 0.0f;

        #pragma unroll
        for (int kp = 0; kp < 4; ++kp) {
            const int ab = arow + kp * 16 + 2 * tig;
            uint32_t ah[4] = {
                *(const uint32_t*)(Qh + ab),
                *(const uint32_t*)(Qh + ab + 8 * A_LD),
                *(const uint32_t*)(Qh + ab + 8),
                *(const uint32_t*)(Qh + ab + 8 * A_LD + 8) };
            uint32_t al[4] = {
                *(const uint32_t*)(Ql + ab),
                *(const uint32_t*)(Ql + ab + 8 * A_LD),
                *(const uint32_t*)(Ql + ab + 8),
                *(const uint32_t*)(Ql + ab + 8 * A_LD + 8) };
            #pragma unroll
            for (int ni = 0; ni < 8; ++ni) {
                const int bbse = (ni * 8 + gid) * A_LD + kp * 16 + 2 * tig;
                uint32_t bhf[2] = { *(const uint32_t*)(Kh + bbse),
                                    *(const uint32_t*)(Kh + bbse + 8) };
                mma16816h(sacc[ni], ah, bhf);
                mma16816h(sacc[ni], al, bhf);
            }
        }

        // ---- online softmax (log2 units) ----
        float t0 = sacc[0][0], t1 = sacc[0][2];
        #pragma unroll
        for (int ni = 0; ni < 8; ++ni) {
            t0 = fmaxf(t0, fmaxf(sacc[ni][0], sacc[ni][1]));
            t1 = fmaxf(t1, fmaxf(sacc[ni][2], sacc[ni][3]));
        }
        t0 = fmaxf(t0, __shfl_xor_sync(0xffffffffu, t0, 1));
        t0 = fmaxf(t0, __shfl_xor_sync(0xffffffffu, t0, 2));
        t1 = fmaxf(t1, __shfl_xor_sync(0xffffffffu, t1, 1));
        t1 = fmaxf(t1, __shfl_xor_sync(0xffffffffu, t1, 2));
        const float nm0 = fmaxf(m0, t0), nm1 = fmaxf(m1, t1);
        const float f0 = ex2f(m0 - nm0), f1 = ex2f(m1 - nm1);
        m0 = nm0; m1 = nm1;
        #pragma unroll
        for (int ni = 0; ni < 8; ++ni) {
            oacc[ni][0] *= f0; oacc[ni][1] *= f0;
            oacc[ni][2] *= f1; oacc[ni][3] *= f1;
        }
        lacc[0] *= f0; lacc[1] *= f0; lacc[2] *= f1; lacc[3] *= f1;

        // ---- p = exp2(s - m), pack fp16, mask via PRMT/AND ----
        uint32_t PH[8][2];
        #pragma unroll
        for (int ni = 0; ni < 8; ++ni) {
            float p0 = ex2f(sacc[ni][0] - nm0);
            float p1 = ex2f(sacc[ni][1] - nm0);
            float p2 = ex2f(sacc[ni][2] - nm1);
            float p3 = ex2f(sacc[ni][3] - nm1);
            const uint32_t mw = Mw[ni];
            PH[ni][0] = packh(p0, p1) & prmt(mw, 0x1100u);
            PH[ni][1] = packh(p2, p3) & prmt(mw, 0x3322u);
        }

        // ---- O += P V (1 MMA); l += P . ones (1 MMA) ----
        const uint32_t ones16[2] = {0x3C003C00u, 0x3C003C00u};
        #pragma unroll
        for (int kp = 0; kp < 4; ++kp) {
            uint32_t aph[4] = { PH[2*kp][0], PH[2*kp][1],
                                PH[2*kp+1][0], PH[2*kp+1][1] };
            mma16816h(lacc, aph, ones16);
            #pragma unroll
            for (int ni = 0; ni < 8; ++ni) {
                const int vb = (ni * 8 + gid) * A_LD + kp * 16 + 2 * tig;
                uint32_t bh2[2] = { *(const uint32_t*)(Vh + vb),
                                    *(const uint32_t*)(Vh + vb + 8) };
                mma16816h(oacc[ni], aph, bh2);
            }
        }
        __syncthreads();
    }

    // ---- normalize + write fp16 hi/lo splits (feeds gemm_out) ----
    const float inv0 = 1.0f / lacc[0];
    const float inv1 = 1.0f / lacc[2];
    const size_t r0 = (size_t)(bb * SEQ + q0 + w * 16 + gid) * DIM + hh * HDIM;
    const size_t r1 = r0 + 8 * DIM;
    #pragma unroll
    for (int ni = 0; ni < 8; ++ni) {
        const int col = ni * 8 + 2 * tig;
        float o0 = oacc[ni][0] * inv0, o1 = oacc[ni][1] * inv0;
        float o2 = oacc[ni][2] * inv1, o3 = oacc[ni][3] * inv1;
        float h0 = __half2float(__float2half(o0));
        float h1 = __half2float(__float2half(o1));
        float h2 = __half2float(__float2half(o2));
        float h3 = __half2float(__float2half(o3));
        *(uint32_t*)(g_a_hi + r0 + col) = packh(h0, h1);
        *(uint32_t*)(g_a_hi + r1 + col) = packh(h2, h3);
        *(uint32_t*)(g_a_lo + r0 + col) = packh(o0 - h0, o1 - h1);
        *(uint32_t*)(g_a_lo + r1 + col) = packh(o2 - h2, o3 - h3);
    }
}

// =============================== launch ====================================
extern "C" void kernel_launch(void* const* d_in, const int* in_sizes, int n_in,
                              void* d_out, int out_size)
{
    const float* q    = (const float*)d_in[0];
    const float* k    = (const float*)d_in[1];
    const float* v    = (const float*)d_in[2];
    const int*   mask = (const int*)  d_in[3];
    const float* w_q  = (const float*)d_in[4];
    const float* b_q  = (const float*)d_in[5];
    const float* w_k  = (const float*)d_in[6];
    const float* b_k  = (const float*)d_in[7];
    const float* w_v  = (const float*)d_in[8];
    const float* b_v  = (const float*)d_in[9];
    const float* w_o  = (const float*)d_in[10];
    const float* b_o  = (const float*)d_in[11];
    float* out = (float*)d_out;

    (void)in_sizes; (void)n_in; (void)out_size;

    cudaFuncSetAttribute(gemm_proj,
                         cudaFuncAttributeMaxDynamicSharedMemorySize, GEMM_SMEM);
    cudaFuncSetAttribute(gemm_out,
                         cudaFuncAttributeMaxDynamicSharedMemorySize, GEMM_SMEM);
    cudaFuncSetAttribute(attn_mma,
                         cudaFuncAttributeMaxDynamicSharedMemorySize, ATTN_SMEM);

    // Pre-passes
    wT_split<<<dim3(32, 32, 4), dim3(32, 8)>>>(w_q, w_k, w_v, w_o);
    split3<<<dim3(4096, 3), 256>>>(q, k, v);
    mask_fragb<<<(SEQ * SEQ / 4) / 256, 256>>>(mask);

    // QKV projections (fp16 2-MMA, 2 CTAs/SM)
    gemm_proj<<<dim3(8, 32, 3), 256, GEMM_SMEM>>>(b_q, b_k, b_v);

    // V transpose -> fp16
    vt_split<<<dim3(SEQ / 32, HDIM / 32, BATCH * NHEAD), dim3(32, 8)>>>();

    // Attention (fp16 tensor cores, 2 CTAs/SM)
    attn_mma<<<dim3(SEQ / 128, NHEAD, BATCH), 256, ATTN_SMEM>>>();

    // Output projection (fp16 2-MMA)
    gemm_out<<<dim3(8, 32), 256, GEMM_SMEM>>>(b_o, out);
}